// round 5
// baseline (speedup 1.0000x reference)
#include <cuda_runtime.h>
#include <cstdint>

#define Hd   2048
#define NHd  16
#define DHd  128
#define Bd   4
#define Sd   2048
#define Ad   512

// ---------------- scratch (static device arrays; no allocation) ----------------
__device__ float g_Q[(size_t)Bd * Sd * Hd];     // 67 MB
__device__ float g_K[(size_t)Bd * Ad * Hd];     // 16.8 MB
__device__ float g_V[(size_t)Bd * Ad * Hd];     // 16.8 MB
__device__ float g_ctx[(size_t)Bd * Sd * Hd];   // 67 MB
__device__ float g_att[(size_t)Bd * Sd * Hd];   // 67 MB

// ---------------- helpers ----------------
__device__ __forceinline__ float to_tf32(float x) {
    uint32_t u;
    asm("cvt.rna.tf32.f32 %0, %1;" : "=r"(u) : "f"(x));
    return __uint_as_float(u);
}

__device__ __forceinline__ void mma_tf32(float c[4], const uint32_t a[4], const uint32_t b[2]) {
    asm volatile(
        "mma.sync.aligned.m16n8k8.row.col.f32.tf32.tf32.f32 "
        "{%0,%1,%2,%3}, {%4,%5,%6,%7}, {%8,%9}, {%0,%1,%2,%3};"
        : "+f"(c[0]), "+f"(c[1]), "+f"(c[2]), "+f"(c[3])
        : "r"(a[0]), "r"(a[1]), "r"(a[2]), "r"(a[3]), "r"(b[0]), "r"(b[1]));
}

// =====================================================================
// GEMM: C[M x 2048] = X[M x 2048] @ W[2048 x 2048] + bias
// Block tile 128x128, BK=16, 256 threads (8 warps, 2x4), warp tile 64x32.
// tf32 mma m16n8k8, fp32 accumulate. M, N divisible by 128 (no guards).
// =====================================================================
__global__ void __launch_bounds__(256) gemm_tf32_kernel(
    const float* __restrict__ X, const float* __restrict__ W,
    const float* __restrict__ bias, float* __restrict__ C)
{
    __shared__ float As[128][20];   // stride 20 -> conflict-free a-frag LDS
    __shared__ float Bs[16][136];   // stride 136 -> conflict-free b-frag LDS

    const int tid  = threadIdx.x;
    const int lane = tid & 31, wid = tid >> 5;
    const int g    = lane >> 2, tig = lane & 3;
    const int wm   = wid >> 2,  wn  = wid & 3;
    const int m0   = blockIdx.y * 128, n0 = blockIdx.x * 128;

    const int ar = tid >> 2;          // 0..63
    const int ac = (tid & 3) * 4;     // 0,4,8,12

    float acc[4][4][4];
    #pragma unroll
    for (int mi = 0; mi < 4; mi++)
        #pragma unroll
        for (int ni = 0; ni < 4; ni++)
            #pragma unroll
            for (int j = 0; j < 4; j++) acc[mi][ni][j] = 0.0f;

    #pragma unroll 1
    for (int k0 = 0; k0 < 2048; k0 += 16) {
        __syncthreads();
        // A tile: 128 x 16
        {
            float4 v0 = *(const float4*)(X + (size_t)(m0 + ar) * 2048 + k0 + ac);
            float4 v1 = *(const float4*)(X + (size_t)(m0 + ar + 64) * 2048 + k0 + ac);
            float4 t0 = make_float4(to_tf32(v0.x), to_tf32(v0.y), to_tf32(v0.z), to_tf32(v0.w));
            float4 t1 = make_float4(to_tf32(v1.x), to_tf32(v1.y), to_tf32(v1.z), to_tf32(v1.w));
            *(float4*)(&As[ar][ac])      = t0;
            *(float4*)(&As[ar + 64][ac]) = t1;
        }
        // B tile: 16 x 128
        #pragma unroll
        for (int p = 0; p < 2; p++) {
            int i = tid + p * 256;
            int r = i >> 5, c = (i & 31) << 2;
            float4 v = *(const float4*)(W + (size_t)(k0 + r) * 2048 + n0 + c);
            float4 t = make_float4(to_tf32(v.x), to_tf32(v.y), to_tf32(v.z), to_tf32(v.w));
            *(float4*)(&Bs[r][c]) = t;
        }
        __syncthreads();

        #pragma unroll
        for (int kk = 0; kk < 16; kk += 8) {
            uint32_t af[4][4];
            #pragma unroll
            for (int mi = 0; mi < 4; mi++) {
                int r = wm * 64 + mi * 16 + g;
                af[mi][0] = __float_as_uint(As[r][kk + tig]);
                af[mi][1] = __float_as_uint(As[r + 8][kk + tig]);
                af[mi][2] = __float_as_uint(As[r][kk + tig + 4]);
                af[mi][3] = __float_as_uint(As[r + 8][kk + tig + 4]);
            }
            uint32_t bf[4][2];
            #pragma unroll
            for (int ni = 0; ni < 4; ni++) {
                int c = wn * 32 + ni * 8 + g;
                bf[ni][0] = __float_as_uint(Bs[kk + tig][c]);
                bf[ni][1] = __float_as_uint(Bs[kk + tig + 4][c]);
            }
            #pragma unroll
            for (int mi = 0; mi < 4; mi++)
                #pragma unroll
                for (int ni = 0; ni < 4; ni++)
                    mma_tf32(acc[mi][ni], af[mi], bf[ni]);
        }
    }

    // epilogue: + bias, write fp32
    #pragma unroll
    for (int mi = 0; mi < 4; mi++) {
        #pragma unroll
        for (int ni = 0; ni < 4; ni++) {
            int r = m0 + wm * 64 + mi * 16 + g;
            int c = n0 + wn * 32 + ni * 8 + tig * 2;
            float b0 = bias[c], b1 = bias[c + 1];
            C[(size_t)r * 2048 + c]              = acc[mi][ni][0] + b0;
            C[(size_t)r * 2048 + c + 1]          = acc[mi][ni][1] + b1;
            C[(size_t)(r + 8) * 2048 + c]        = acc[mi][ni][2] + b0;
            C[(size_t)(r + 8) * 2048 + c + 1]    = acc[mi][ni][3] + b1;
        }
    }
}

// =====================================================================
// Fused attention per (b, h, 64-row q tile):
//   S = Q Kᵀ / sqrt(DH) + mask*(-1e4)   (64 x 512, in smem)
//   P = softmax(S)                       (warp-per-8-rows)
//   ctx = P V                            (64 x 128 -> global)
// Dynamic smem: Qs 64x132 + KVs 64x132 + Ssc 64x516 + mask 512 = 201,728 B
// =====================================================================
#define ATTN_SMEM_FLOATS (64 * 132 * 2 + 64 * 516 + 512)
#define ATTN_SMEM_BYTES  (ATTN_SMEM_FLOATS * 4)

__global__ void __launch_bounds__(256) attn_kernel(const float* __restrict__ mask)
{
    extern __shared__ float smf[];
    float* Qs  = smf;                    // 64*132
    float* KVs = smf + 64 * 132;         // 64*132
    float* Ssc = smf + 2 * 64 * 132;     // 64*516
    float* mv  = Ssc + 64 * 516;         // 512

    const int tid  = threadIdx.x;
    const int lane = tid & 31, wid = tid >> 5;
    const int g    = lane >> 2, tig = lane & 3;
    const int wm   = wid >> 2,  wn  = wid & 3;

    const int bx = blockIdx.x;
    const int qt = bx & 31;
    const int h  = (bx >> 5) & 15;
    const int b  = bx >> 9;
    const int qrow0 = b * Sd + qt * 64;
    const int krow0 = b * Ad;
    const int hoff  = h * DHd;
    const float scale = 0.0883883476483184f;   // 1/sqrt(128)

    // ---- load Q tile (tf32) ----
    #pragma unroll
    for (int p = 0; p < 8; p++) {
        int i = tid + p * 256;
        int r = i >> 5, c = (i & 31) << 2;
        float4 v = *(const float4*)(g_Q + (size_t)(qrow0 + r) * Hd + hoff + c);
        float* dst = Qs + r * 132 + c;
        dst[0] = to_tf32(v.x); dst[1] = to_tf32(v.y);
        dst[2] = to_tf32(v.z); dst[3] = to_tf32(v.w);
    }
    // mask: 512 entries, 256 threads -> each thread loads TWO (bugfix from R2:
    // `if (tid < 512)` only covered 0..255, leaving mv[256..512) uninitialized)
    mv[tid]       = mask[b * Ad + tid]       * -10000.0f;
    mv[tid + 256] = mask[b * Ad + tid + 256] * -10000.0f;

    // ---- phase 1: scores ----
    #pragma unroll 1
    for (int kc = 0; kc < 8; kc++) {
        __syncthreads();
        #pragma unroll
        for (int p = 0; p < 8; p++) {
            int i = tid + p * 256;
            int r = i >> 5, c = (i & 31) << 2;
            float4 v = *(const float4*)(g_K + (size_t)(krow0 + kc * 64 + r) * Hd + hoff + c);
            float* dst = KVs + r * 132 + c;
            dst[0] = to_tf32(v.x); dst[1] = to_tf32(v.y);
            dst[2] = to_tf32(v.z); dst[3] = to_tf32(v.w);
        }
        __syncthreads();

        float acc[2][2][4];
        #pragma unroll
        for (int mi = 0; mi < 2; mi++)
            #pragma unroll
            for (int ni = 0; ni < 2; ni++)
                #pragma unroll
                for (int j = 0; j < 4; j++) acc[mi][ni][j] = 0.0f;

        #pragma unroll
        for (int kk = 0; kk < 128; kk += 8) {
            uint32_t af[2][4];
            #pragma unroll
            for (int mi = 0; mi < 2; mi++) {
                int r = wm * 32 + mi * 16 + g;
                af[mi][0] = __float_as_uint(Qs[r * 132 + kk + tig]);
                af[mi][1] = __float_as_uint(Qs[(r + 8) * 132 + kk + tig]);
                af[mi][2] = __float_as_uint(Qs[r * 132 + kk + tig + 4]);
                af[mi][3] = __float_as_uint(Qs[(r + 8) * 132 + kk + tig + 4]);
            }
            uint32_t bf[2][2];
            #pragma unroll
            for (int ni = 0; ni < 2; ni++) {
                int ac = wn * 16 + ni * 8 + g;
                bf[ni][0] = __float_as_uint(KVs[ac * 132 + kk + tig]);
                bf[ni][1] = __float_as_uint(KVs[ac * 132 + kk + tig + 4]);
            }
            #pragma unroll
            for (int mi = 0; mi < 2; mi++)
                #pragma unroll
                for (int ni = 0; ni < 2; ni++)
                    mma_tf32(acc[mi][ni], af[mi], bf[ni]);
        }

        #pragma unroll
        for (int mi = 0; mi < 2; mi++) {
            #pragma unroll
            for (int ni = 0; ni < 2; ni++) {
                int sr  = wm * 32 + mi * 16 + g;
                int col = kc * 64 + wn * 16 + ni * 8 + tig * 2;
                float m0 = mv[col], m1 = mv[col + 1];
                Ssc[sr * 516 + col]           = acc[mi][ni][0] * scale + m0;
                Ssc[sr * 516 + col + 1]       = acc[mi][ni][1] * scale + m1;
                Ssc[(sr + 8) * 516 + col]     = acc[mi][ni][2] * scale + m0;
                Ssc[(sr + 8) * 516 + col + 1] = acc[mi][ni][3] * scale + m1;
            }
        }
    }
    __syncthreads();

    // ---- phase 2: softmax (warp handles 8 rows) ----
    #pragma unroll 1
    for (int r8 = 0; r8 < 8; r8++) {
        int sr = wid * 8 + r8;
        float vals[16];
        float mx = -1e30f;
        #pragma unroll
        for (int j = 0; j < 16; j++) {
            vals[j] = Ssc[sr * 516 + lane + j * 32];
            mx = fmaxf(mx, vals[j]);
        }
        #pragma unroll
        for (int o = 16; o > 0; o >>= 1)
            mx = fmaxf(mx, __shfl_xor_sync(0xffffffffu, mx, o));
        float sum = 0.0f;
        #pragma unroll
        for (int j = 0; j < 16; j++) { vals[j] = __expf(vals[j] - mx); sum += vals[j]; }
        #pragma unroll
        for (int o = 16; o > 0; o >>= 1)
            sum += __shfl_xor_sync(0xffffffffu, sum, o);
        float inv = 1.0f / sum;
        #pragma unroll
        for (int j = 0; j < 16; j++)
            Ssc[sr * 516 + lane + j * 32] = to_tf32(vals[j] * inv);
    }

    // ---- phase 3: ctx = P @ V ----
    float acc3[2][4][4];
    #pragma unroll
    for (int mi = 0; mi < 2; mi++)
        #pragma unroll
        for (int ni = 0; ni < 4; ni++)
            #pragma unroll
            for (int j = 0; j < 4; j++) acc3[mi][ni][j] = 0.0f;

    #pragma unroll 1
    for (int vc = 0; vc < 8; vc++) {
        __syncthreads();
        #pragma unroll
        for (int p = 0; p < 8; p++) {
            int i = tid + p * 256;
            int r = i >> 5, c = (i & 31) << 2;
            float4 v = *(const float4*)(g_V + (size_t)(krow0 + vc * 64 + r) * Hd + hoff + c);
            float* dst = KVs + r * 132 + c;
            dst[0] = to_tf32(v.x); dst[1] = to_tf32(v.y);
            dst[2] = to_tf32(v.z); dst[3] = to_tf32(v.w);
        }
        __syncthreads();

        #pragma unroll
        for (int kk = 0; kk < 64; kk += 8) {
            uint32_t af[2][4];
            #pragma unroll
            for (int mi = 0; mi < 2; mi++) {
                int r = wm * 32 + mi * 16 + g;
                int c = vc * 64 + kk + tig;
                af[mi][0] = __float_as_uint(Ssc[r * 516 + c]);
                af[mi][1] = __float_as_uint(Ssc[(r + 8) * 516 + c]);
                af[mi][2] = __float_as_uint(Ssc[r * 516 + c + 4]);
                af[mi][3] = __float_as_uint(Ssc[(r + 8) * 516 + c + 4]);
            }
            uint32_t bf[4][2];
            #pragma unroll
            for (int ni = 0; ni < 4; ni++) {
                int dc = wn * 32 + ni * 8 + g;
                bf[ni][0] = __float_as_uint(KVs[(kk + tig) * 132 + dc]);
                bf[ni][1] = __float_as_uint(KVs[(kk + tig + 4) * 132 + dc]);
            }
            #pragma unroll
            for (int mi = 0; mi < 2; mi++)
                #pragma unroll
                for (int ni = 0; ni < 4; ni++)
                    mma_tf32(acc3[mi][ni], af[mi], bf[ni]);
        }
    }

    #pragma unroll
    for (int mi = 0; mi < 2; mi++) {
        #pragma unroll
        for (int ni = 0; ni < 4; ni++) {
            int sr = wm * 32 + mi * 16 + g;
            int dc = wn * 32 + ni * 8 + tig * 2;
            size_t base = (size_t)(qrow0 + sr) * Hd + hoff + dc;
            g_ctx[base]                = acc3[mi][ni][0];
            g_ctx[base + 1]            = acc3[mi][ni][1];
            g_ctx[base + 8 * Hd]       = acc3[mi][ni][2];
            g_ctx[base + 8 * Hd + 1]   = acc3[mi][ni][3];
        }
    }
}

// =====================================================================
// Residual + LayerNorm: out = LN(att + hidden) * gamma + beta
// one block per row (2048 cols), 256 threads
// =====================================================================
__global__ void __launch_bounds__(256) ln_kernel(
    const float* __restrict__ att, const float* __restrict__ hid,
    const float* __restrict__ gamma, const float* __restrict__ beta,
    float* __restrict__ out)
{
    const int row = blockIdx.x, t = threadIdx.x;
    const float4* a4 = (const float4*)(att + (size_t)row * Hd);
    const float4* h4 = (const float4*)(hid + (size_t)row * Hd);

    float4 xv[2];
    float s = 0.0f, ss = 0.0f;
    #pragma unroll
    for (int p = 0; p < 2; p++) {
        int i = t + p * 256;
        float4 a = a4[i], hh = h4[i];
        float4 x = make_float4(a.x + hh.x, a.y + hh.y, a.z + hh.z, a.w + hh.w);
        xv[p] = x;
        s  += x.x + x.y + x.z + x.w;
        ss += x.x * x.x + x.y * x.y + x.z * x.z + x.w * x.w;
    }
    __shared__ float rs[8], rss[8];
    #pragma unroll
    for (int o = 16; o > 0; o >>= 1) {
        s  += __shfl_xor_sync(0xffffffffu, s, o);
        ss += __shfl_xor_sync(0xffffffffu, ss, o);
    }
    if ((t & 31) == 0) { rs[t >> 5] = s; rss[t >> 5] = ss; }
    __syncthreads();
    float ts = 0.0f, tss = 0.0f;
    #pragma unroll
    for (int i = 0; i < 8; i++) { ts += rs[i]; tss += rss[i]; }
    const float mean = ts * (1.0f / Hd);
    const float var  = tss * (1.0f / Hd) - mean * mean;
    const float inv  = rsqrtf(var + 1e-5f);

    const float4* g4 = (const float4*)gamma;
    const float4* b4 = (const float4*)beta;
    float4* o4 = (float4*)(out + (size_t)row * Hd);
    #pragma unroll
    for (int p = 0; p < 2; p++) {
        int i = t + p * 256;
        float4 gv = g4[i], bv = b4[i], x = xv[p];
        float4 y = make_float4((x.x - mean) * inv * gv.x + bv.x,
                               (x.y - mean) * inv * gv.y + bv.y,
                               (x.z - mean) * inv * gv.z + bv.z,
                               (x.w - mean) * inv * gv.w + bv.w);
        o4[i] = y;
    }
}

// =====================================================================
// launcher
// =====================================================================
extern "C" void kernel_launch(void* const* d_in, const int* in_sizes, int n_in,
                              void* d_out, int out_size)
{
    const float* hidden = (const float*)d_in[0];
    const float* audio  = (const float*)d_in[1];
    const float* amask  = (const float*)d_in[2];
    const float* Wq = (const float*)d_in[3];
    const float* bq = (const float*)d_in[4];
    const float* Wk = (const float*)d_in[5];
    const float* bk = (const float*)d_in[6];
    const float* Wv = (const float*)d_in[7];
    const float* bv = (const float*)d_in[8];
    const float* Wo = (const float*)d_in[9];
    const float* bo = (const float*)d_in[10];
    const float* gamma = (const float*)d_in[11];
    const float* beta  = (const float*)d_in[12];
    float* out = (float*)d_out;

    float *Qp, *Kp, *Vp, *Cp, *Ap;
    cudaGetSymbolAddress((void**)&Qp, g_Q);
    cudaGetSymbolAddress((void**)&Kp, g_K);
    cudaGetSymbolAddress((void**)&Vp, g_V);
    cudaGetSymbolAddress((void**)&Cp, g_ctx);
    cudaGetSymbolAddress((void**)&Ap, g_att);

    cudaFuncSetAttribute(attn_kernel, cudaFuncAttributeMaxDynamicSharedMemorySize,
                         ATTN_SMEM_BYTES);

    // Q = hidden @ Wq + bq        (8192 x 2048)
    gemm_tf32_kernel<<<dim3(16, 64), 256>>>(hidden, Wq, bq, Qp);
    // K = audio @ Wk + bk         (2048 x 2048)
    gemm_tf32_kernel<<<dim3(16, 16), 256>>>(audio, Wk, bk, Kp);
    // V = audio @ Wv + bv
    gemm_tf32_kernel<<<dim3(16, 16), 256>>>(audio, Wv, bv, Vp);
    // fused attention -> g_ctx
    attn_kernel<<<Bd * NHd * (Sd / 64), 256, ATTN_SMEM_BYTES>>>(amask);
    // out_proj = ctx @ Wo + bo -> g_att
    gemm_tf32_kernel<<<dim3(16, 64), 256>>>(Cp, Wo, bo, Ap);
    // residual + LayerNorm -> d_out
    ln_kernel<<<Bd * Sd, 256>>>(Ap, hidden, gamma, beta, out);
}

// round 6
// speedup vs baseline: 1.1306x; 1.1306x over previous
#include <cuda_runtime.h>
#include <cstdint>

#define Hd   2048
#define NHd  16
#define DHd  128
#define Bd   4
#define Sd   2048
#define Ad   512

// ---------------- scratch (static device arrays; no allocation) ----------------
__device__ float g_Q[(size_t)Bd * Sd * Hd];
__device__ float g_K[(size_t)Bd * Ad * Hd];
__device__ float g_V[(size_t)Bd * Ad * Hd];
__device__ float g_ctx[(size_t)Bd * Sd * Hd];
__device__ float g_att[(size_t)Bd * Sd * Hd];

// ---------------- helpers ----------------
__device__ __forceinline__ void cp16(void* dst, const void* src) {
    uint32_t d = (uint32_t)__cvta_generic_to_shared(dst);
    asm volatile("cp.async.cg.shared.global [%0], [%1], 16;\n" :: "r"(d), "l"(src));
}
#define CP_COMMIT asm volatile("cp.async.commit_group;\n" ::: "memory")
#define CP_WAIT0  asm volatile("cp.async.wait_group 0;\n" ::: "memory")

// raw fp32 bits into tf32 mma: HW truncates mantissa (RZ). rel_err budget ok.
__device__ __forceinline__ void mma_tf32(float c[4], const uint32_t a[4], const uint32_t b[2]) {
    asm volatile(
        "mma.sync.aligned.m16n8k8.row.col.f32.tf32.tf32.f32 "
        "{%0,%1,%2,%3}, {%4,%5,%6,%7}, {%8,%9}, {%0,%1,%2,%3};"
        : "+f"(c[0]), "+f"(c[1]), "+f"(c[2]), "+f"(c[3])
        : "r"(a[0]), "r"(a[1]), "r"(a[2]), "r"(a[3]), "r"(b[0]), "r"(b[1]));
}

// =====================================================================
// GEMM: C[M x 2048] = X[M x 2048] @ W[2048 x 2048] + bias
// 128x128 tile, BK=16, 256 threads (8 warps 2x4, warp tile 64x32),
// 2-stage cp.async double buffering. tf32 mma, fp32 accum.
// =====================================================================
__global__ void __launch_bounds__(256) gemm_tf32_kernel(
    const float* __restrict__ X, const float* __restrict__ W,
    const float* __restrict__ bias, float* __restrict__ C)
{
    __shared__ float As[2][128][20];   // 20-stride: conflict-free a-frag LDS, 16B aligned rows
    __shared__ float Bs[2][16][136];   // 136-stride: conflict-free b-frag LDS

    const int tid  = threadIdx.x;
    const int lane = tid & 31, wid = tid >> 5;
    const int g    = lane >> 2, tig = lane & 3;
    const int wm   = wid >> 2,  wn  = wid & 3;
    const int m0   = blockIdx.y * 128, n0 = blockIdx.x * 128;

    const int ar = tid >> 2;          // 0..63
    const int ac = (tid & 3) * 4;     // 0,4,8,12
    const int br = tid >> 5;          // 0..7
    const int bc = (tid & 31) * 4;    // 0..124

    float acc[4][4][4];
    #pragma unroll
    for (int mi = 0; mi < 4; mi++)
        #pragma unroll
        for (int ni = 0; ni < 4; ni++)
            #pragma unroll
            for (int j = 0; j < 4; j++) acc[mi][ni][j] = 0.0f;

    auto load_stage = [&](int st, int k0) {
        cp16(&As[st][ar][ac],      X + (size_t)(m0 + ar) * 2048 + k0 + ac);
        cp16(&As[st][ar + 64][ac], X + (size_t)(m0 + ar + 64) * 2048 + k0 + ac);
        cp16(&Bs[st][br][bc],      W + (size_t)(k0 + br) * 2048 + n0 + bc);
        cp16(&Bs[st][br + 8][bc],  W + (size_t)(k0 + br + 8) * 2048 + n0 + bc);
        CP_COMMIT;
    };

    load_stage(0, 0);
    int st = 0;

    #pragma unroll 1
    for (int k0 = 0; k0 < 2048; k0 += 16) {
        CP_WAIT0;
        __syncthreads();
        if (k0 + 16 < 2048) load_stage(st ^ 1, k0 + 16);

        #pragma unroll
        for (int kk = 0; kk < 16; kk += 8) {
            uint32_t af[4][4];
            #pragma unroll
            for (int mi = 0; mi < 4; mi++) {
                int r = wm * 64 + mi * 16 + g;
                af[mi][0] = __float_as_uint(As[st][r][kk + tig]);
                af[mi][1] = __float_as_uint(As[st][r + 8][kk + tig]);
                af[mi][2] = __float_as_uint(As[st][r][kk + tig + 4]);
                af[mi][3] = __float_as_uint(As[st][r + 8][kk + tig + 4]);
            }
            uint32_t bf[4][2];
            #pragma unroll
            for (int ni = 0; ni < 4; ni++) {
                int c = wn * 32 + ni * 8 + g;
                bf[ni][0] = __float_as_uint(Bs[st][kk + tig][c]);
                bf[ni][1] = __float_as_uint(Bs[st][kk + tig + 4][c]);
            }
            #pragma unroll
            for (int mi = 0; mi < 4; mi++)
                #pragma unroll
                for (int ni = 0; ni < 4; ni++)
                    mma_tf32(acc[mi][ni], af[mi], bf[ni]);
        }
        st ^= 1;
    }

    #pragma unroll
    for (int mi = 0; mi < 4; mi++) {
        #pragma unroll
        for (int ni = 0; ni < 4; ni++) {
            int r = m0 + wm * 64 + mi * 16 + g;
            int c = n0 + wn * 32 + ni * 8 + tig * 2;
            float b0 = bias[c], b1 = bias[c + 1];
            C[(size_t)r * 2048 + c]           = acc[mi][ni][0] + b0;
            C[(size_t)r * 2048 + c + 1]       = acc[mi][ni][1] + b1;
            C[(size_t)(r + 8) * 2048 + c]     = acc[mi][ni][2] + b0;
            C[(size_t)(r + 8) * 2048 + c + 1] = acc[mi][ni][3] + b1;
        }
    }
}

// =====================================================================
// Fused attention per (b, h, 64-row q tile).
// cp.async staging; V chunks double-buffered through the (dead) Q buffer.
// Dynamic smem: Qs 64x132 + KVs 64x132 + Ssc 64x516 + mask 512 = 201,728 B
// =====================================================================
#define ATTN_SMEM_FLOATS (64 * 132 * 2 + 64 * 516 + 512)
#define ATTN_SMEM_BYTES  (ATTN_SMEM_FLOATS * 4)

__global__ void __launch_bounds__(256) attn_kernel(const float* __restrict__ mask)
{
    extern __shared__ float smf[];
    float* Qs  = smf;                    // 64*132  (phase3: V buffer for odd chunks)
    float* KVs = smf + 64 * 132;         // 64*132  (K chunks; phase3: V even chunks)
    float* Ssc = smf + 2 * 64 * 132;     // 64*516
    float* mv  = Ssc + 64 * 516;         // 512

    const int tid  = threadIdx.x;
    const int lane = tid & 31, wid = tid >> 5;
    const int g    = lane >> 2, tig = lane & 3;
    const int wm   = wid >> 2,  wn  = wid & 3;

    const int bx = blockIdx.x;
    const int qt = bx & 31;
    const int h  = (bx >> 5) & 15;
    const int b  = bx >> 9;
    const int qrow0 = b * Sd + qt * 64;
    const int krow0 = b * Ad;
    const int hoff  = h * DHd;
    const float scale = 0.0883883476483184f;   // 1/sqrt(128)

    // 64x128-float tile copy: 2048 float4, 8 per thread
    auto load_tile = [&](float* dst, const float* src_base) {
        #pragma unroll
        for (int p = 0; p < 8; p++) {
            int i = tid + p * 256;
            int r = i >> 5, c = (i & 31) << 2;
            cp16(dst + r * 132 + c, src_base + (size_t)r * Hd + c);
        }
        CP_COMMIT;
    };

    // prologue: Q tile + K chunk 0 in flight
    load_tile(Qs, g_Q + (size_t)qrow0 * Hd + hoff);
    load_tile(KVs, g_K + (size_t)krow0 * Hd + hoff);
    mv[tid]       = mask[b * Ad + tid]       * -10000.0f;
    mv[tid + 256] = mask[b * Ad + tid + 256] * -10000.0f;

    // ---- phase 1: scores ----
    #pragma unroll 1
    for (int kc = 0; kc < 8; kc++) {
        CP_WAIT0;
        __syncthreads();

        float acc[2][2][4];
        #pragma unroll
        for (int mi = 0; mi < 2; mi++)
            #pragma unroll
            for (int ni = 0; ni < 2; ni++)
                #pragma unroll
                for (int j = 0; j < 4; j++) acc[mi][ni][j] = 0.0f;

        #pragma unroll
        for (int kk = 0; kk < 128; kk += 8) {
            uint32_t af[2][4];
            #pragma unroll
            for (int mi = 0; mi < 2; mi++) {
                int r = wm * 32 + mi * 16 + g;
                af[mi][0] = __float_as_uint(Qs[r * 132 + kk + tig]);
                af[mi][1] = __float_as_uint(Qs[(r + 8) * 132 + kk + tig]);
                af[mi][2] = __float_as_uint(Qs[r * 132 + kk + tig + 4]);
                af[mi][3] = __float_as_uint(Qs[(r + 8) * 132 + kk + tig + 4]);
            }
            uint32_t bf[2][2];
            #pragma unroll
            for (int ni = 0; ni < 2; ni++) {
                int ac = wn * 16 + ni * 8 + g;
                bf[ni][0] = __float_as_uint(KVs[ac * 132 + kk + tig]);
                bf[ni][1] = __float_as_uint(KVs[ac * 132 + kk + tig + 4]);
            }
            #pragma unroll
            for (int mi = 0; mi < 2; mi++)
                #pragma unroll
                for (int ni = 0; ni < 2; ni++)
                    mma_tf32(acc[mi][ni], af[mi], bf[ni]);
        }

        #pragma unroll
        for (int mi = 0; mi < 2; mi++) {
            #pragma unroll
            for (int ni = 0; ni < 2; ni++) {
                int sr  = wm * 32 + mi * 16 + g;
                int col = kc * 64 + wn * 16 + ni * 8 + tig * 2;
                float m0 = mv[col], m1 = mv[col + 1];
                Ssc[sr * 516 + col]           = acc[mi][ni][0] * scale + m0;
                Ssc[sr * 516 + col + 1]       = acc[mi][ni][1] * scale + m1;
                Ssc[(sr + 8) * 516 + col]     = acc[mi][ni][2] * scale + m0;
                Ssc[(sr + 8) * 516 + col + 1] = acc[mi][ni][3] * scale + m1;
            }
        }
        __syncthreads();   // all reads of KVs done before overwrite
        if (kc < 7) load_tile(KVs, g_K + (size_t)(krow0 + (kc + 1) * 64) * Hd + hoff);
        else        load_tile(KVs, g_V + (size_t)krow0 * Hd + hoff);  // prefetch V0 under softmax
    }

    // ---- phase 2: softmax (warp per 8 rows); V0 load in flight ----
    #pragma unroll 1
    for (int r8 = 0; r8 < 8; r8++) {
        int sr = wid * 8 + r8;
        float vals[16];
        float mx = -1e30f;
        #pragma unroll
        for (int j = 0; j < 16; j++) {
            vals[j] = Ssc[sr * 516 + lane + j * 32];
            mx = fmaxf(mx, vals[j]);
        }
        #pragma unroll
        for (int o = 16; o > 0; o >>= 1)
            mx = fmaxf(mx, __shfl_xor_sync(0xffffffffu, mx, o));
        float sum = 0.0f;
        #pragma unroll
        for (int j = 0; j < 16; j++) { vals[j] = __expf(vals[j] - mx); sum += vals[j]; }
        #pragma unroll
        for (int o = 16; o > 0; o >>= 1)
            sum += __shfl_xor_sync(0xffffffffu, sum, o);
        float inv = 1.0f / sum;
        #pragma unroll
        for (int j = 0; j < 16; j++)
            Ssc[sr * 516 + lane + j * 32] = vals[j] * inv;
    }

    // ---- phase 3: ctx = P @ V, V chunks ping-pong KVs/Qs ----
    float acc3[2][4][4];
    #pragma unroll
    for (int mi = 0; mi < 2; mi++)
        #pragma unroll
        for (int ni = 0; ni < 4; ni++)
            #pragma unroll
            for (int j = 0; j < 4; j++) acc3[mi][ni][j] = 0.0f;

    #pragma unroll 1
    for (int vc = 0; vc < 8; vc++) {
        CP_WAIT0;
        __syncthreads();   // chunk vc ready; also fences softmax writes (vc==0)
        // prefetch vc+1 into the other buffer (its last readers finished before the sync above)
        if (vc < 7)
            load_tile((vc & 1) ? KVs : Qs,
                      g_V + (size_t)(krow0 + (vc + 1) * 64) * Hd + hoff);
        const float* Vb = (vc & 1) ? Qs : KVs;

        #pragma unroll
        for (int kk = 0; kk < 64; kk += 8) {
            uint32_t af[2][4];
            #pragma unroll
            for (int mi = 0; mi < 2; mi++) {
                int r = wm * 32 + mi * 16 + g;
                int c = vc * 64 + kk + tig;
                af[mi][0] = __float_as_uint(Ssc[r * 516 + c]);
                af[mi][1] = __float_as_uint(Ssc[(r + 8) * 516 + c]);
                af[mi][2] = __float_as_uint(Ssc[r * 516 + c + 4]);
                af[mi][3] = __float_as_uint(Ssc[(r + 8) * 516 + c + 4]);
            }
            uint32_t bf[4][2];
            #pragma unroll
            for (int ni = 0; ni < 4; ni++) {
                int dc = wn * 32 + ni * 8 + g;
                bf[ni][0] = __float_as_uint(Vb[(kk + tig) * 132 + dc]);
                bf[ni][1] = __float_as_uint(Vb[(kk + tig + 4) * 132 + dc]);
            }
            #pragma unroll
            for (int mi = 0; mi < 2; mi++)
                #pragma unroll
                for (int ni = 0; ni < 4; ni++)
                    mma_tf32(acc3[mi][ni], af[mi], bf[ni]);
        }
    }

    #pragma unroll
    for (int mi = 0; mi < 2; mi++) {
        #pragma unroll
        for (int ni = 0; ni < 4; ni++) {
            int sr = wm * 32 + mi * 16 + g;
            int dc = wn * 32 + ni * 8 + tig * 2;
            size_t base = (size_t)(qrow0 + sr) * Hd + hoff + dc;
            g_ctx[base]              = acc3[mi][ni][0];
            g_ctx[base + 1]          = acc3[mi][ni][1];
            g_ctx[base + 8 * Hd]     = acc3[mi][ni][2];
            g_ctx[base + 8 * Hd + 1] = acc3[mi][ni][3];
        }
    }
}

// =====================================================================
// Residual + LayerNorm
// =====================================================================
__global__ void __launch_bounds__(256) ln_kernel(
    const float* __restrict__ att, const float* __restrict__ hid,
    const float* __restrict__ gamma, const float* __restrict__ beta,
    float* __restrict__ out)
{
    const int row = blockIdx.x, t = threadIdx.x;
    const float4* a4 = (const float4*)(att + (size_t)row * Hd);
    const float4* h4 = (const float4*)(hid + (size_t)row * Hd);

    float4 xv[2];
    float s = 0.0f, ss = 0.0f;
    #pragma unroll
    for (int p = 0; p < 2; p++) {
        int i = t + p * 256;
        float4 a = a4[i], hh = h4[i];
        float4 x = make_float4(a.x + hh.x, a.y + hh.y, a.z + hh.z, a.w + hh.w);
        xv[p] = x;
        s  += x.x + x.y + x.z + x.w;
        ss += x.x * x.x + x.y * x.y + x.z * x.z + x.w * x.w;
    }
    __shared__ float rs[8], rss[8];
    #pragma unroll
    for (int o = 16; o > 0; o >>= 1) {
        s  += __shfl_xor_sync(0xffffffffu, s, o);
        ss += __shfl_xor_sync(0xffffffffu, ss, o);
    }
    if ((t & 31) == 0) { rs[t >> 5] = s; rss[t >> 5] = ss; }
    __syncthreads();
    float ts = 0.0f, tss = 0.0f;
    #pragma unroll
    for (int i = 0; i < 8; i++) { ts += rs[i]; tss += rss[i]; }
    const float mean = ts * (1.0f / Hd);
    const float var  = tss * (1.0f / Hd) - mean * mean;
    const float inv  = rsqrtf(var + 1e-5f);

    const float4* g4 = (const float4*)gamma;
    const float4* b4 = (const float4*)beta;
    float4* o4 = (float4*)(out + (size_t)row * Hd);
    #pragma unroll
    for (int p = 0; p < 2; p++) {
        int i = t + p * 256;
        float4 gv = g4[i], bv = b4[i], x = xv[p];
        o4[i] = make_float4((x.x - mean) * inv * gv.x + bv.x,
                            (x.y - mean) * inv * gv.y + bv.y,
                            (x.z - mean) * inv * gv.z + bv.z,
                            (x.w - mean) * inv * gv.w + bv.w);
    }
}

// =====================================================================
// launcher
// =====================================================================
extern "C" void kernel_launch(void* const* d_in, const int* in_sizes, int n_in,
                              void* d_out, int out_size)
{
    const float* hidden = (const float*)d_in[0];
    const float* audio  = (const float*)d_in[1];
    const float* amask  = (const float*)d_in[2];
    const float* Wq = (const float*)d_in[3];
    const float* bq = (const float*)d_in[4];
    const float* Wk = (const float*)d_in[5];
    const float* bk = (const float*)d_in[6];
    const float* Wv = (const float*)d_in[7];
    const float* bv = (const float*)d_in[8];
    const float* Wo = (const float*)d_in[9];
    const float* bo = (const float*)d_in[10];
    const float* gamma = (const float*)d_in[11];
    const float* beta  = (const float*)d_in[12];
    float* out = (float*)d_out;

    float *Qp, *Kp, *Vp, *Cp, *Ap;
    cudaGetSymbolAddress((void**)&Qp, g_Q);
    cudaGetSymbolAddress((void**)&Kp, g_K);
    cudaGetSymbolAddress((void**)&Vp, g_V);
    cudaGetSymbolAddress((void**)&Cp, g_ctx);
    cudaGetSymbolAddress((void**)&Ap, g_att);

    cudaFuncSetAttribute(attn_kernel, cudaFuncAttributeMaxDynamicSharedMemorySize,
                         ATTN_SMEM_BYTES);

    gemm_tf32_kernel<<<dim3(16, 64), 256>>>(hidden, Wq, bq, Qp);
    gemm_tf32_kernel<<<dim3(16, 16), 256>>>(audio, Wk, bk, Kp);
    gemm_tf32_kernel<<<dim3(16, 16), 256>>>(audio, Wv, bv, Vp);
    attn_kernel<<<Bd * NHd * (Sd / 64), 256, ATTN_SMEM_BYTES>>>(amask);
    gemm_tf32_kernel<<<dim3(16, 64), 256>>>(Cp, Wo, bo, Ap);
    ln_kernel<<<Bd * Sd, 256>>>(Ap, hidden, gamma, beta, out);
}

// round 9
// speedup vs baseline: 1.6443x; 1.4543x over previous
#include <cuda_runtime.h>
#include <cuda_fp16.h>
#include <cstdint>

#define Hd   2048
#define NHd  16
#define DHd  128
#define Bd   4
#define Sd   2048
#define Ad   512

// ---------------- scratch (static device arrays; no allocation) ----------------
__device__ __half g_hidh[(size_t)Bd * Sd * Hd];   // hidden fp16
__device__ __half g_audh[(size_t)Bd * Ad * Hd];   // audio fp16
__device__ __half g_Wh[4][(size_t)Hd * Hd];       // transposed fp16 weights [n][k]
__device__ __half g_Qh[(size_t)Bd * Sd * Hd];
__device__ __half g_Kh[(size_t)Bd * Ad * Hd];
__device__ __half g_Vh[(size_t)Bd * Ad * Hd];
__device__ __half g_ctxh[(size_t)Bd * Sd * Hd];
__device__ float  g_att[(size_t)Bd * Sd * Hd];

// ---------------- helpers ----------------
__device__ __forceinline__ void cp16(void* dst, const void* src) {
    uint32_t d = (uint32_t)__cvta_generic_to_shared(dst);
    asm volatile("cp.async.cg.shared.global [%0], [%1], 16;\n" :: "r"(d), "l"(src));
}
#define CP_COMMIT asm volatile("cp.async.commit_group;\n" ::: "memory")
#define CP_WAIT0  asm volatile("cp.async.wait_group 0;\n" ::: "memory")

__device__ __forceinline__ void mma_f16(float c[4], const uint32_t a[4], const uint32_t b[2]) {
    asm volatile(
        "mma.sync.aligned.m16n8k16.row.col.f32.f16.f16.f32 "
        "{%0,%1,%2,%3}, {%4,%5,%6,%7}, {%8,%9}, {%0,%1,%2,%3};"
        : "+f"(c[0]), "+f"(c[1]), "+f"(c[2]), "+f"(c[3])
        : "r"(a[0]), "r"(a[1]), "r"(a[2]), "r"(a[3]), "r"(b[0]), "r"(b[1]));
}

__device__ __forceinline__ uint32_t packf2(float a, float b) {
    __half2 h = __floats2half2_rn(a, b);
    return *(uint32_t*)&h;
}
__device__ __forceinline__ uint32_t packh2(__half a, __half b) {
    __half2 h = __halves2half2(a, b);
    return *(uint32_t*)&h;
}

// =====================================================================
// fp32 -> fp16 elementwise (n divisible by 4)
// =====================================================================
__global__ void __launch_bounds__(256) f2h_kernel(
    const float* __restrict__ in, __half* __restrict__ out)
{
    int i = blockIdx.x * 256 + threadIdx.x;
    float4 v = ((const float4*)in)[i];
    __half2* o2 = (__half2*)out;
    o2[2 * i]     = __floats2half2_rn(v.x, v.y);
    o2[2 * i + 1] = __floats2half2_rn(v.z, v.w);
}

// =====================================================================
// transpose + convert: out[n][k] = (half) in[k][n]   (2048 x 2048)
// =====================================================================
__global__ void __launch_bounds__(256) transpose_h_kernel(
    const float* __restrict__ in, __half* __restrict__ out)
{
    __shared__ float t[32][33];
    const int bx = blockIdx.x * 32, by = blockIdx.y * 32;
    const int tx = threadIdx.x, ty = threadIdx.y;   // block (32, 8)
    #pragma unroll
    for (int r = 0; r < 32; r += 8)
        t[ty + r][tx] = in[(size_t)(by + ty + r) * Hd + bx + tx];
    __syncthreads();
    #pragma unroll
    for (int r = 0; r < 32; r += 8)
        out[(size_t)(bx + ty + r) * Hd + by + tx] = __float2half_rn(t[tx][ty + r]);
}

// =====================================================================
// fp16 GEMM: C[M x 2048] = X[M x 2048] @ W + bias
//   X fp16 [m][k]; Wt fp16 [n][k] (pre-transposed) -> both K-major.
//   128x128 tile, BK=32, 256 threads (8 warps 2x4, warp tile 64x32),
//   2-stage cp.async. m16n8k16 f16 mma, fp32 accum.
// =====================================================================
template<bool HALF_OUT>
__global__ void __launch_bounds__(256) gemm_h_kernel(
    const __half* __restrict__ X, const __half* __restrict__ Wt,
    const float* __restrict__ bias, void* __restrict__ Cout)
{
    __shared__ __half As[2][128][40];   // 40-half stride: conflict-free frag LDS
    __shared__ __half Bs[2][128][40];

    const int tid  = threadIdx.x;
    const int lane = tid & 31, wid = tid >> 5;
    const int g    = lane >> 2, tig = lane & 3;
    const int wm   = wid >> 2,  wn  = wid & 3;
    const int m0   = blockIdx.y * 128, n0 = blockIdx.x * 128;

    const int r_ld = tid >> 1;          // 0..127
    const int c_ld = (tid & 1) * 16;    // 0 or 16 (halves)

    float acc[4][4][4];
    #pragma unroll
    for (int mi = 0; mi < 4; mi++)
        #pragma unroll
        for (int ni = 0; ni < 4; ni++)
            #pragma unroll
            for (int j = 0; j < 4; j++) acc[mi][ni][j] = 0.0f;

    auto load_stage = [&](int st, int k0) {
        const __half* xs = X  + (size_t)(m0 + r_ld) * Hd + k0 + c_ld;
        cp16(&As[st][r_ld][c_ld],     xs);
        cp16(&As[st][r_ld][c_ld + 8], xs + 8);
        const __half* ws = Wt + (size_t)(n0 + r_ld) * Hd + k0 + c_ld;
        cp16(&Bs[st][r_ld][c_ld],     ws);
        cp16(&Bs[st][r_ld][c_ld + 8], ws + 8);
        CP_COMMIT;
    };

    load_stage(0, 0);
    int st = 0;

    #pragma unroll 1
    for (int k0 = 0; k0 < Hd; k0 += 32) {
        CP_WAIT0;
        __syncthreads();
        if (k0 + 32 < Hd) load_stage(st ^ 1, k0 + 32);

        #pragma unroll
        for (int kk = 0; kk < 32; kk += 16) {
            uint32_t af[4][4];
            #pragma unroll
            for (int mi = 0; mi < 4; mi++) {
                int r = wm * 64 + mi * 16 + g;
                af[mi][0] = *(const uint32_t*)&As[st][r][kk + 2 * tig];
                af[mi][1] = *(const uint32_t*)&As[st][r + 8][kk + 2 * tig];
                af[mi][2] = *(const uint32_t*)&As[st][r][kk + 2 * tig + 8];
                af[mi][3] = *(const uint32_t*)&As[st][r + 8][kk + 2 * tig + 8];
            }
            uint32_t bf[4][2];
            #pragma unroll
            for (int ni = 0; ni < 4; ni++) {
                int n = wn * 32 + ni * 8 + g;
                bf[ni][0] = *(const uint32_t*)&Bs[st][n][kk + 2 * tig];
                bf[ni][1] = *(const uint32_t*)&Bs[st][n][kk + 2 * tig + 8];
            }
            #pragma unroll
            for (int mi = 0; mi < 4; mi++)
                #pragma unroll
                for (int ni = 0; ni < 4; ni++)
                    mma_f16(acc[mi][ni], af[mi], bf[ni]);
        }
        st ^= 1;
    }

    #pragma unroll
    for (int mi = 0; mi < 4; mi++) {
        #pragma unroll
        for (int ni = 0; ni < 4; ni++) {
            int r = m0 + wm * 64 + mi * 16 + g;
            int c = n0 + wn * 32 + ni * 8 + tig * 2;
            float b0 = bias[c], b1 = bias[c + 1];
            if (HALF_OUT) {
                __half* C = (__half*)Cout;
                *(__half2*)(C + (size_t)r * Hd + c) =
                    __floats2half2_rn(acc[mi][ni][0] + b0, acc[mi][ni][1] + b1);
                *(__half2*)(C + (size_t)(r + 8) * Hd + c) =
                    __floats2half2_rn(acc[mi][ni][2] + b0, acc[mi][ni][3] + b1);
            } else {
                float* C = (float*)Cout;
                *(float2*)(C + (size_t)r * Hd + c) =
                    make_float2(acc[mi][ni][0] + b0, acc[mi][ni][1] + b1);
                *(float2*)(C + (size_t)(r + 8) * Hd + c) =
                    make_float2(acc[mi][ni][2] + b0, acc[mi][ni][3] + b1);
            }
        }
    }
}

// =====================================================================
// Fused attention per (b, h, 64-row q tile). fp16 Q/K/V tiles + f16 mma,
// fp32 scores + softmax, P converted to half2 on the fly.
// Dyn smem: Qs 64x136 h + KVs 64x136 h + Ssc 64x516 f + mask 512 f = 168,960 B
// =====================================================================
#define SM_QS   0
#define SM_KVS  17408
#define SM_SSC  34816
#define SM_MV   166912
#define ATTN_SMEM_BYTES 168960

__global__ void __launch_bounds__(256) attn_kernel(const float* __restrict__ mask)
{
    extern __shared__ char smc[];
    __half (*Qs)[136]  = (__half (*)[136])(smc + SM_QS);
    __half (*KVs)[136] = (__half (*)[136])(smc + SM_KVS);
    float* Ssc = (float*)(smc + SM_SSC);       // [64][516]
    float* mv  = (float*)(smc + SM_MV);        // [512]

    const int tid  = threadIdx.x;
    const int lane = tid & 31, wid = tid >> 5;
    const int g    = lane >> 2, tig = lane & 3;
    const int wm   = wid >> 2,  wn  = wid & 3;

    const int bx = blockIdx.x;
    const int qt = bx & 31;
    const int h  = (bx >> 5) & 15;
    const int b  = bx >> 9;
    const int qrow0 = b * Sd + qt * 64;
    const int krow0 = b * Ad;
    const int hoff  = h * DHd;
    const float scale = 0.0883883476483184f;   // 1/sqrt(128)

    // 64x128-half tile: 1024 cp16, 4 per thread
    auto load_tile = [&](__half (*dst)[136], const __half* src_base) {
        #pragma unroll
        for (int p = 0; p < 4; p++) {
            int i = tid + p * 256;
            int r = i >> 4, c = (i & 15) * 8;
            cp16(&dst[r][c], src_base + (size_t)r * Hd + c);
        }
        CP_COMMIT;
    };

    load_tile(Qs,  g_Qh + (size_t)qrow0 * Hd + hoff);
    load_tile(KVs, g_Kh + (size_t)krow0 * Hd + hoff);
    mv[tid]       = mask[b * Ad + tid]       * -10000.0f;
    mv[tid + 256] = mask[b * Ad + tid + 256] * -10000.0f;

    // ---- phase 1: scores ----
    #pragma unroll 1
    for (int kc = 0; kc < 8; kc++) {
        CP_WAIT0;
        __syncthreads();

        float acc[2][2][4];
        #pragma unroll
        for (int mi = 0; mi < 2; mi++)
            #pragma unroll
            for (int ni = 0; ni < 2; ni++)
                #pragma unroll
                for (int j = 0; j < 4; j++) acc[mi][ni][j] = 0.0f;

        #pragma unroll
        for (int kk = 0; kk < 128; kk += 16) {
            uint32_t af[2][4];
            #pragma unroll
            for (int mi = 0; mi < 2; mi++) {
                int r = wm * 32 + mi * 16 + g;
                af[mi][0] = *(const uint32_t*)&Qs[r][kk + 2 * tig];
                af[mi][1] = *(const uint32_t*)&Qs[r + 8][kk + 2 * tig];
                af[mi][2] = *(const uint32_t*)&Qs[r][kk + 2 * tig + 8];
                af[mi][3] = *(const uint32_t*)&Qs[r + 8][kk + 2 * tig + 8];
            }
            uint32_t bf[2][2];
            #pragma unroll
            for (int ni = 0; ni < 2; ni++) {
                int ac = wn * 16 + ni * 8 + g;
                bf[ni][0] = *(const uint32_t*)&KVs[ac][kk + 2 * tig];
                bf[ni][1] = *(const uint32_t*)&KVs[ac][kk + 2 * tig + 8];
            }
            #pragma unroll
            for (int mi = 0; mi < 2; mi++)
                #pragma unroll
                for (int ni = 0; ni < 2; ni++)
                    mma_f16(acc[mi][ni], af[mi], bf[ni]);
        }

        #pragma unroll
        for (int mi = 0; mi < 2; mi++) {
            #pragma unroll
            for (int ni = 0; ni < 2; ni++) {
                int sr  = wm * 32 + mi * 16 + g;
                int col = kc * 64 + wn * 16 + ni * 8 + tig * 2;
                float m0 = mv[col], m1 = mv[col + 1];
                Ssc[sr * 516 + col]           = acc[mi][ni][0] * scale + m0;
                Ssc[sr * 516 + col + 1]       = acc[mi][ni][1] * scale + m1;
                Ssc[(sr + 8) * 516 + col]     = acc[mi][ni][2] * scale + m0;
                Ssc[(sr + 8) * 516 + col + 1] = acc[mi][ni][3] * scale + m1;
            }
        }
        __syncthreads();
        if (kc < 7) load_tile(KVs, g_Kh + (size_t)(krow0 + (kc + 1) * 64) * Hd + hoff);
        else        load_tile(KVs, g_Vh + (size_t)krow0 * Hd + hoff);  // V0 under softmax
    }

    // ---- phase 2: softmax (warp per 8 rows), fp32 in Ssc ----
    #pragma unroll 1
    for (int r8 = 0; r8 < 8; r8++) {
        int sr = wid * 8 + r8;
        float vals[16];
        float mx = -1e30f;
        #pragma unroll
        for (int j = 0; j < 16; j++) {
            vals[j] = Ssc[sr * 516 + lane + j * 32];
            mx = fmaxf(mx, vals[j]);
        }
        #pragma unroll
        for (int o = 16; o > 0; o >>= 1)
            mx = fmaxf(mx, __shfl_xor_sync(0xffffffffu, mx, o));
        float sum = 0.0f;
        #pragma unroll
        for (int j = 0; j < 16; j++) { vals[j] = __expf(vals[j] - mx); sum += vals[j]; }
        #pragma unroll
        for (int o = 16; o > 0; o >>= 1)
            sum += __shfl_xor_sync(0xffffffffu, sum, o);
        float inv = 1.0f / sum;
        #pragma unroll
        for (int j = 0; j < 16; j++)
            Ssc[sr * 516 + lane + j * 32] = vals[j] * inv;
    }

    // ---- phase 3: ctx = P @ V ----
    float acc3[2][4][4];
    #pragma unroll
    for (int mi = 0; mi < 2; mi++)
        #pragma unroll
        for (int ni = 0; ni < 4; ni++)
            #pragma unroll
            for (int j = 0; j < 4; j++) acc3[mi][ni][j] = 0.0f;

    #pragma unroll 1
    for (int vc = 0; vc < 8; vc++) {
        CP_WAIT0;
        __syncthreads();
        if (vc < 7)
            load_tile((vc & 1) ? KVs : Qs,
                      g_Vh + (size_t)(krow0 + (vc + 1) * 64) * Hd + hoff);
        const __half (*Vb)[136] = (vc & 1) ? Qs : KVs;

        #pragma unroll
        for (int kk = 0; kk < 64; kk += 16) {
            uint32_t af[2][4];
            #pragma unroll
            for (int mi = 0; mi < 2; mi++) {
                int r = wm * 32 + mi * 16 + g;
                int c = vc * 64 + kk + 2 * tig;
                const float* p0 = Ssc + r * 516 + c;
                const float* p1 = Ssc + (r + 8) * 516 + c;
                af[mi][0] = packf2(p0[0], p0[1]);
                af[mi][1] = packf2(p1[0], p1[1]);
                af[mi][2] = packf2(p0[8], p0[9]);
                af[mi][3] = packf2(p1[8], p1[9]);
            }
            uint32_t bf[4][2];
            #pragma unroll
            for (int ni = 0; ni < 4; ni++) {
                int dc = wn * 32 + ni * 8 + g;
                int k0 = kk + 2 * tig;
                bf[ni][0] = packh2(Vb[k0][dc],     Vb[k0 + 1][dc]);
                bf[ni][1] = packh2(Vb[k0 + 8][dc], Vb[k0 + 9][dc]);
            }
            #pragma unroll
            for (int mi = 0; mi < 2; mi++)
                #pragma unroll
                for (int ni = 0; ni < 4; ni++)
                    mma_f16(acc3[mi][ni], af[mi], bf[ni]);
        }
    }

    #pragma unroll
    for (int mi = 0; mi < 2; mi++) {
        #pragma unroll
        for (int ni = 0; ni < 4; ni++) {
            int sr = wm * 32 + mi * 16 + g;
            int dc = wn * 32 + ni * 8 + tig * 2;
            size_t base = (size_t)(qrow0 + sr) * Hd + hoff + dc;
            *(__half2*)(g_ctxh + base) =
                __floats2half2_rn(acc3[mi][ni][0], acc3[mi][ni][1]);
            *(__half2*)(g_ctxh + base + 8 * Hd) =
                __floats2half2_rn(acc3[mi][ni][2], acc3[mi][ni][3]);
        }
    }
}

// =====================================================================
// Residual + LayerNorm: out = LN(att + hidden) * gamma + beta
// =====================================================================
__global__ void __launch_bounds__(256) ln_kernel(
    const float* __restrict__ att, const float* __restrict__ hid,
    const float* __restrict__ gamma, const float* __restrict__ beta,
    float* __restrict__ out)
{
    const int row = blockIdx.x, t = threadIdx.x;
    const float4* a4 = (const float4*)(att + (size_t)row * Hd);
    const float4* h4 = (const float4*)(hid + (size_t)row * Hd);

    float4 xv[2];
    float s = 0.0f, ss = 0.0f;
    #pragma unroll
    for (int p = 0; p < 2; p++) {
        int i = t + p * 256;
        float4 a = a4[i], hh = h4[i];
        float4 x = make_float4(a.x + hh.x, a.y + hh.y, a.z + hh.z, a.w + hh.w);
        xv[p] = x;
        s  += x.x + x.y + x.z + x.w;
        ss += x.x * x.x + x.y * x.y + x.z * x.z + x.w * x.w;
    }
    __shared__ float rs[8], rss[8];
    #pragma unroll
    for (int o = 16; o > 0; o >>= 1) {
        s  += __shfl_xor_sync(0xffffffffu, s, o);
        ss += __shfl_xor_sync(0xffffffffu, ss, o);
    }
    if ((t & 31) == 0) { rs[t >> 5] = s; rss[t >> 5] = ss; }
    __syncthreads();
    float ts = 0.0f, tss = 0.0f;
    #pragma unroll
    for (int i = 0; i < 8; i++) { ts += rs[i]; tss += rss[i]; }
    const float mean = ts * (1.0f / Hd);
    const float var  = tss * (1.0f / Hd) - mean * mean;
    const float inv  = rsqrtf(var + 1e-5f);

    const float4* g4 = (const float4*)gamma;
    const float4* b4 = (const float4*)beta;
    float4* o4 = (float4*)(out + (size_t)row * Hd);
    #pragma unroll
    for (int p = 0; p < 2; p++) {
        int i = t + p * 256;
        float4 gv = g4[i], bv = b4[i], x = xv[p];
        o4[i] = make_float4((x.x - mean) * inv * gv.x + bv.x,
                            (x.y - mean) * inv * gv.y + bv.y,
                            (x.z - mean) * inv * gv.z + bv.z,
                            (x.w - mean) * inv * gv.w + bv.w);
    }
}

// =====================================================================
// launcher
// =====================================================================
extern "C" void kernel_launch(void* const* d_in, const int* in_sizes, int n_in,
                              void* d_out, int out_size)
{
    const float* hidden = (const float*)d_in[0];
    const float* audio  = (const float*)d_in[1];
    const float* amask  = (const float*)d_in[2];
    const float* Wq = (const float*)d_in[3];
    const float* bq = (const float*)d_in[4];
    const float* Wk = (const float*)d_in[5];
    const float* bk = (const float*)d_in[6];
    const float* Wv = (const float*)d_in[7];
    const float* bv = (const float*)d_in[8];
    const float* Wo = (const float*)d_in[9];
    const float* bo = (const float*)d_in[10];
    const float* gamma = (const float*)d_in[11];
    const float* beta  = (const float*)d_in[12];
    float* out = (float*)d_out;

    __half *hidh, *audh, *Wh, *Qh, *Kh, *Vh, *ctxh;
    float* attp;
    cudaGetSymbolAddress((void**)&hidh, g_hidh);
    cudaGetSymbolAddress((void**)&audh, g_audh);
    cudaGetSymbolAddress((void**)&Wh,   g_Wh);
    cudaGetSymbolAddress((void**)&Qh,   g_Qh);
    cudaGetSymbolAddress((void**)&Kh,   g_Kh);
    cudaGetSymbolAddress((void**)&Vh,   g_Vh);
    cudaGetSymbolAddress((void**)&ctxh, g_ctxh);
    cudaGetSymbolAddress((void**)&attp, g_att);
    __half* WqT = Wh;
    __half* WkT = Wh + (size_t)Hd * Hd;
    __half* WvT = Wh + 2 * (size_t)Hd * Hd;
    __half* WoT = Wh + 3 * (size_t)Hd * Hd;

    cudaFuncSetAttribute(attn_kernel, cudaFuncAttributeMaxDynamicSharedMemorySize,
                         ATTN_SMEM_BYTES);

    // converts
    f2h_kernel<<<(Bd * Sd * Hd) / 1024, 256>>>(hidden, hidh);
    f2h_kernel<<<(Bd * Ad * Hd) / 1024, 256>>>(audio, audh);
    dim3 tg(Hd / 32, Hd / 32), tb(32, 8);
    transpose_h_kernel<<<tg, tb>>>(Wq, WqT);
    transpose_h_kernel<<<tg, tb>>>(Wk, WkT);
    transpose_h_kernel<<<tg, tb>>>(Wv, WvT);
    transpose_h_kernel<<<tg, tb>>>(Wo, WoT);

    // projections (fp16 in/out)
    gemm_h_kernel<true><<<dim3(16, (Bd * Sd) / 128), 256>>>(hidh, WqT, bq, Qh);
    gemm_h_kernel<true><<<dim3(16, (Bd * Ad) / 128), 256>>>(audh, WkT, bk, Kh);
    gemm_h_kernel<true><<<dim3(16, (Bd * Ad) / 128), 256>>>(audh, WvT, bv, Vh);
    // fused attention -> ctx (fp16)
    attn_kernel<<<Bd * NHd * (Sd / 64), 256, ATTN_SMEM_BYTES>>>(amask);
    // out_proj (fp32 out) + residual LN
    gemm_h_kernel<false><<<dim3(16, (Bd * Sd) / 128), 256>>>(ctxh, WoT, bo, attp);
    ln_kernel<<<Bd * Sd, 256>>>(attp, hidden, gamma, beta, out);
}

// round 12
// speedup vs baseline: 1.9240x; 1.1701x over previous
#include <cuda_runtime.h>
#include <cuda_fp16.h>
#include <cstdint>

#define Hd   2048
#define NHd  16
#define DHd  128
#define Bd   4
#define Sd   2048
#define Ad   512

// ---------------- scratch (static device arrays; no allocation) ----------------
__device__ __half g_hidh[(size_t)Bd * Sd * Hd];
__device__ __half g_audh[(size_t)Bd * Ad * Hd];
__device__ __half g_Wh[4][(size_t)Hd * Hd];       // transposed fp16 weights [n][k]
__device__ __half g_Qh[(size_t)Bd * Sd * Hd];
__device__ __half g_Kh[(size_t)Bd * Ad * Hd];
__device__ __half g_Vh[(size_t)Bd * Ad * Hd];
__device__ __half g_ctxh[(size_t)Bd * Sd * Hd];
__device__ float  g_att[(size_t)Bd * Sd * Hd];

// ---------------- helpers ----------------
__device__ __forceinline__ void cp16(void* dst, const void* src) {
    uint32_t d = (uint32_t)__cvta_generic_to_shared(dst);
    asm volatile("cp.async.cg.shared.global [%0], [%1], 16;\n" :: "r"(d), "l"(src));
}
#define CP_COMMIT asm volatile("cp.async.commit_group;\n" ::: "memory")
#define CP_WAIT0  asm volatile("cp.async.wait_group 0;\n" ::: "memory")

__device__ __forceinline__ uint32_t smaddr(const void* p) {
    return (uint32_t)__cvta_generic_to_shared(p);
}

__device__ __forceinline__ void ldm4(uint32_t r[4], uint32_t a) {
    asm volatile("ldmatrix.sync.aligned.m8n8.x4.shared.b16 {%0,%1,%2,%3}, [%4];"
                 : "=r"(r[0]), "=r"(r[1]), "=r"(r[2]), "=r"(r[3]) : "r"(a));
}

__device__ __forceinline__ void mma_f16(float c[4], const uint32_t a[4], const uint32_t b[2]) {
    asm volatile(
        "mma.sync.aligned.m16n8k16.row.col.f32.f16.f16.f32 "
        "{%0,%1,%2,%3}, {%4,%5,%6,%7}, {%8,%9}, {%0,%1,%2,%3};"
        : "+f"(c[0]), "+f"(c[1]), "+f"(c[2]), "+f"(c[3])
        : "r"(a[0]), "r"(a[1]), "r"(a[2]), "r"(a[3]), "r"(b[0]), "r"(b[1]));
}

__device__ __forceinline__ uint32_t packh2(__half a, __half b) {
    __half2 h = __halves2half2(a, b);
    return *(uint32_t*)&h;
}

// =====================================================================
// fp32 -> fp16 elementwise
// =====================================================================
__global__ void __launch_bounds__(256) f2h_kernel(
    const float* __restrict__ in, __half* __restrict__ out)
{
    int i = blockIdx.x * 256 + threadIdx.x;
    float4 v = ((const float4*)in)[i];
    __half2* o2 = (__half2*)out;
    o2[2 * i]     = __floats2half2_rn(v.x, v.y);
    o2[2 * i + 1] = __floats2half2_rn(v.z, v.w);
}

// =====================================================================
// transpose + convert: out[n][k] = (half) in[k][n]
// =====================================================================
__global__ void __launch_bounds__(256) transpose_h_kernel(
    const float* __restrict__ in, __half* __restrict__ out)
{
    __shared__ float t[32][33];
    const int bx = blockIdx.x * 32, by = blockIdx.y * 32;
    const int tx = threadIdx.x, ty = threadIdx.y;
    #pragma unroll
    for (int r = 0; r < 32; r += 8)
        t[ty + r][tx] = in[(size_t)(by + ty + r) * Hd + bx + tx];
    __syncthreads();
    #pragma unroll
    for (int r = 0; r < 32; r += 8)
        out[(size_t)(bx + ty + r) * Hd + by + tx] = __float2half_rn(t[tx][ty + r]);
}

// =====================================================================
// fp16 GEMM with ldmatrix fragment loads.
// 128x128 tile, BK=32, 256 threads (8 warps 2x4, warp tile 64x32),
// 2-stage cp.async. m16n8k16 f16 mma, fp32 accum.
// =====================================================================
template<bool HALF_OUT>
__global__ void __launch_bounds__(256) gemm_h_kernel(
    const __half* __restrict__ X, const __half* __restrict__ Wt,
    const float* __restrict__ bias, void* __restrict__ Cout)
{
    __shared__ __half As[2][128][40];
    __shared__ __half Bs[2][128][40];

    const int tid  = threadIdx.x;
    const int lane = tid & 31, wid = tid >> 5;
    const int g    = lane >> 2, tig = lane & 3;
    const int wm   = wid >> 2,  wn  = wid & 3;
    const int m0   = blockIdx.y * 128, n0 = blockIdx.x * 128;

    const int r_ld = tid >> 1;
    const int c_ld = (tid & 1) * 16;

    // ldmatrix lane geometry (same for A and B, both K-major):
    // segments: 0 -> rows+0..7 @ kk, 1 -> rows+8..15 @ kk, 2 -> rows+0..7 @ kk+8, 3 -> rows+8..15 @ kk+8
    const int lm_r = (lane & 7) + ((lane >> 3) & 1) * 8;
    const int lm_c = (lane >> 4) * 8;

    float acc[4][4][4];
    #pragma unroll
    for (int mi = 0; mi < 4; mi++)
        #pragma unroll
        for (int ni = 0; ni < 4; ni++)
            #pragma unroll
            for (int j = 0; j < 4; j++) acc[mi][ni][j] = 0.0f;

    auto load_stage = [&](int st, int k0) {
        const __half* xs = X  + (size_t)(m0 + r_ld) * Hd + k0 + c_ld;
        cp16(&As[st][r_ld][c_ld],     xs);
        cp16(&As[st][r_ld][c_ld + 8], xs + 8);
        const __half* ws = Wt + (size_t)(n0 + r_ld) * Hd + k0 + c_ld;
        cp16(&Bs[st][r_ld][c_ld],     ws);
        cp16(&Bs[st][r_ld][c_ld + 8], ws + 8);
        CP_COMMIT;
    };

    load_stage(0, 0);
    int st = 0;

    #pragma unroll 1
    for (int k0 = 0; k0 < Hd; k0 += 32) {
        CP_WAIT0;
        __syncthreads();
        if (k0 + 32 < Hd) load_stage(st ^ 1, k0 + 32);

        #pragma unroll
        for (int kk = 0; kk < 32; kk += 16) {
            // A frags: tile order matches a0..a3 of m16n8k16
            uint32_t af[4][4];
            #pragma unroll
            for (int mi = 0; mi < 4; mi++)
                ldm4(af[mi], smaddr(&As[st][wm * 64 + mi * 16 + lm_r][kk + lm_c]));
            // B frags: x4 covers two ni tiles; segs 0/1 -> ni: (k,k+8), segs 2/3 -> ni+1
            // lane row = n + (lane&7) + (lane>>4)*8 ; col = kk + ((lane>>3)&1)*8
            uint32_t bf[4][2];
            #pragma unroll
            for (int nb = 0; nb < 2; nb++) {
                uint32_t t4[4];
                int nrow = wn * 32 + nb * 16 + (lane & 7) + (lane >> 4) * 8;
                int ncol = kk + ((lane >> 3) & 1) * 8;
                ldm4(t4, smaddr(&Bs[st][nrow][ncol]));
                bf[2 * nb][0]     = t4[0];
                bf[2 * nb][1]     = t4[1];
                bf[2 * nb + 1][0] = t4[2];
                bf[2 * nb + 1][1] = t4[3];
            }
            #pragma unroll
            for (int mi = 0; mi < 4; mi++)
                #pragma unroll
                for (int ni = 0; ni < 4; ni++)
                    mma_f16(acc[mi][ni], af[mi], bf[ni]);
        }
        st ^= 1;
    }

    #pragma unroll
    for (int mi = 0; mi < 4; mi++) {
        #pragma unroll
        for (int ni = 0; ni < 4; ni++) {
            int r = m0 + wm * 64 + mi * 16 + g;
            int c = n0 + wn * 32 + ni * 8 + tig * 2;
            float b0 = bias[c], b1 = bias[c + 1];
            if (HALF_OUT) {
                __half* C = (__half*)Cout;
                *(__half2*)(C + (size_t)r * Hd + c) =
                    __floats2half2_rn(acc[mi][ni][0] + b0, acc[mi][ni][1] + b1);
                *(__half2*)(C + (size_t)(r + 8) * Hd + c) =
                    __floats2half2_rn(acc[mi][ni][2] + b0, acc[mi][ni][3] + b1);
            } else {
                float* C = (float*)Cout;
                *(float2*)(C + (size_t)r * Hd + c) =
                    make_float2(acc[mi][ni][0] + b0, acc[mi][ni][1] + b1);
                *(float2*)(C + (size_t)(r + 8) * Hd + c) =
                    make_float2(acc[mi][ni][2] + b0, acc[mi][ni][3] + b1);
            }
        }
    }
}

// =====================================================================
// Fused attention. fp16 Q/K/V tiles, fp16 score buffer (fp32 softmax math).
// smem: Qs 64x136h (17408) + KVs 64x136h (17408) + Ssc 64x520h (66560)
//       + mv 512f (2048) = 103,424 B  -> 2 CTAs/SM
// =====================================================================
#define SM_QS   0
#define SM_KVS  17408
#define SM_SSC  34816
#define SM_MV   101376
#define ATTN_SMEM_BYTES 103424
#define SSTR    520

__global__ void __launch_bounds__(256) attn_kernel(const float* __restrict__ mask)
{
    extern __shared__ char smc[];
    __half (*Qs)[136]  = (__half (*)[136])(smc + SM_QS);
    __half (*KVs)[136] = (__half (*)[136])(smc + SM_KVS);
    __half* Ssc = (__half*)(smc + SM_SSC);     // [64][SSTR]
    float* mv   = (float*)(smc + SM_MV);       // [512]

    const int tid  = threadIdx.x;
    const int lane = tid & 31, wid = tid >> 5;
    const int g    = lane >> 2, tig = lane & 3;
    const int wm   = wid >> 2,  wn  = wid & 3;

    const int bx = blockIdx.x;
    const int qt = bx & 31;
    const int h  = (bx >> 5) & 15;
    const int b  = bx >> 9;
    const int qrow0 = b * Sd + qt * 64;
    const int krow0 = b * Ad;
    const int hoff  = h * DHd;
    const float scale = 0.0883883476483184f;   // 1/sqrt(128)

    auto load_tile = [&](__half (*dst)[136], const __half* src_base) {
        #pragma unroll
        for (int p = 0; p < 4; p++) {
            int i = tid + p * 256;
            int r = i >> 4, c = (i & 15) * 8;
            cp16(&dst[r][c], src_base + (size_t)r * Hd + c);
        }
        CP_COMMIT;
    };

    load_tile(Qs,  g_Qh + (size_t)qrow0 * Hd + hoff);
    load_tile(KVs, g_Kh + (size_t)krow0 * Hd + hoff);
    mv[tid]       = mask[b * Ad + tid]       * -10000.0f;
    mv[tid + 256] = mask[b * Ad + tid + 256] * -10000.0f;

    // ---- phase 1: scores -> fp16 Ssc ----
    #pragma unroll 1
    for (int kc = 0; kc < 8; kc++) {
        CP_WAIT0;
        __syncthreads();

        float acc[2][2][4];
        #pragma unroll
        for (int mi = 0; mi < 2; mi++)
            #pragma unroll
            for (int ni = 0; ni < 2; ni++)
                #pragma unroll
                for (int j = 0; j < 4; j++) acc[mi][ni][j] = 0.0f;

        #pragma unroll
        for (int kk = 0; kk < 128; kk += 16) {
            uint32_t af[2][4];
            #pragma unroll
            for (int mi = 0; mi < 2; mi++) {
                int r = wm * 32 + mi * 16 + g;
                af[mi][0] = *(const uint32_t*)&Qs[r][kk + 2 * tig];
                af[mi][1] = *(const uint32_t*)&Qs[r + 8][kk + 2 * tig];
                af[mi][2] = *(const uint32_t*)&Qs[r][kk + 2 * tig + 8];
                af[mi][3] = *(const uint32_t*)&Qs[r + 8][kk + 2 * tig + 8];
            }
            uint32_t bf[2][2];
            #pragma unroll
            for (int ni = 0; ni < 2; ni++) {
                int ac = wn * 16 + ni * 8 + g;
                bf[ni][0] = *(const uint32_t*)&KVs[ac][kk + 2 * tig];
                bf[ni][1] = *(const uint32_t*)&KVs[ac][kk + 2 * tig + 8];
            }
            #pragma unroll
            for (int mi = 0; mi < 2; mi++)
                #pragma unroll
                for (int ni = 0; ni < 2; ni++)
                    mma_f16(acc[mi][ni], af[mi], bf[ni]);
        }

        #pragma unroll
        for (int mi = 0; mi < 2; mi++) {
            #pragma unroll
            for (int ni = 0; ni < 2; ni++) {
                int sr  = wm * 32 + mi * 16 + g;
                int col = kc * 64 + wn * 16 + ni * 8 + tig * 2;
                float m0 = mv[col], m1 = mv[col + 1];
                *(__half2*)&Ssc[sr * SSTR + col] =
                    __floats2half2_rn(acc[mi][ni][0] * scale + m0,
                                      acc[mi][ni][1] * scale + m1);
                *(__half2*)&Ssc[(sr + 8) * SSTR + col] =
                    __floats2half2_rn(acc[mi][ni][2] * scale + m0,
                                      acc[mi][ni][3] * scale + m1);
            }
        }
        __syncthreads();
        if (kc < 7) load_tile(KVs, g_Kh + (size_t)(krow0 + (kc + 1) * 64) * Hd + hoff);
        else        load_tile(KVs, g_Vh + (size_t)krow0 * Hd + hoff);
    }

    // ---- phase 2: softmax (fp32 math, fp16 storage) ----
    #pragma unroll 1
    for (int r8 = 0; r8 < 8; r8++) {
        int sr = wid * 8 + r8;
        float vals[16];
        float mx = -1e30f;
        #pragma unroll
        for (int j = 0; j < 16; j++) {
            vals[j] = __half2float(Ssc[sr * SSTR + lane + j * 32]);
            mx = fmaxf(mx, vals[j]);
        }
        #pragma unroll
        for (int o = 16; o > 0; o >>= 1)
            mx = fmaxf(mx, __shfl_xor_sync(0xffffffffu, mx, o));
        float sum = 0.0f;
        #pragma unroll
        for (int j = 0; j < 16; j++) { vals[j] = __expf(vals[j] - mx); sum += vals[j]; }
        #pragma unroll
        for (int o = 16; o > 0; o >>= 1)
            sum += __shfl_xor_sync(0xffffffffu, sum, o);
        float inv = 1.0f / sum;
        #pragma unroll
        for (int j = 0; j < 16; j++)
            Ssc[sr * SSTR + lane + j * 32] = __float2half_rn(vals[j] * inv);
    }

    // ---- phase 3: ctx = P @ V (P read directly as half2 pairs) ----
    float acc3[2][4][4];
    #pragma unroll
    for (int mi = 0; mi < 2; mi++)
        #pragma unroll
        for (int ni = 0; ni < 4; ni++)
            #pragma unroll
            for (int j = 0; j < 4; j++) acc3[mi][ni][j] = 0.0f;

    #pragma unroll 1
    for (int vc = 0; vc < 8; vc++) {
        CP_WAIT0;
        __syncthreads();
        if (vc < 7)
            load_tile((vc & 1) ? KVs : Qs,
                      g_Vh + (size_t)(krow0 + (vc + 1) * 64) * Hd + hoff);
        const __half (*Vb)[136] = (vc & 1) ? Qs : KVs;

        #pragma unroll
        for (int kk = 0; kk < 64; kk += 16) {
            uint32_t af[2][4];
            #pragma unroll
            for (int mi = 0; mi < 2; mi++) {
                int r = wm * 32 + mi * 16 + g;
                int c = vc * 64 + kk + 2 * tig;
                af[mi][0] = *(const uint32_t*)&Ssc[r * SSTR + c];
                af[mi][1] = *(const uint32_t*)&Ssc[(r + 8) * SSTR + c];
                af[mi][2] = *(const uint32_t*)&Ssc[r * SSTR + c + 8];
                af[mi][3] = *(const uint32_t*)&Ssc[(r + 8) * SSTR + c + 8];
            }
            uint32_t bf[4][2];
            #pragma unroll
            for (int ni = 0; ni < 4; ni++) {
                int dc = wn * 32 + ni * 8 + g;
                int k0 = kk + 2 * tig;
                bf[ni][0] = packh2(Vb[k0][dc],     Vb[k0 + 1][dc]);
                bf[ni][1] = packh2(Vb[k0 + 8][dc], Vb[k0 + 9][dc]);
            }
            #pragma unroll
            for (int mi = 0; mi < 2; mi++)
                #pragma unroll
                for (int ni = 0; ni < 4; ni++)
                    mma_f16(acc3[mi][ni], af[mi], bf[ni]);
        }
    }

    #pragma unroll
    for (int mi = 0; mi < 2; mi++) {
        #pragma unroll
        for (int ni = 0; ni < 4; ni++) {
            int sr = wm * 32 + mi * 16 + g;
            int dc = wn * 32 + ni * 8 + tig * 2;
            size_t base = (size_t)(qrow0 + sr) * Hd + hoff + dc;
            *(__half2*)(g_ctxh + base) =
                __floats2half2_rn(acc3[mi][ni][0], acc3[mi][ni][1]);
            *(__half2*)(g_ctxh + base + 8 * Hd) =
                __floats2half2_rn(acc3[mi][ni][2], acc3[mi][ni][3]);
        }
    }
}

// =====================================================================
// Residual + LayerNorm
// =====================================================================
__global__ void __launch_bounds__(256) ln_kernel(
    const float* __restrict__ att, const float* __restrict__ hid,
    const float* __restrict__ gamma, const float* __restrict__ beta,
    float* __restrict__ out)
{
    const int row = blockIdx.x, t = threadIdx.x;
    const float4* a4 = (const float4*)(att + (size_t)row * Hd);
    const float4* h4 = (const float4*)(hid + (size_t)row * Hd);

    float4 xv[2];
    float s = 0.0f, ss = 0.0f;
    #pragma unroll
    for (int p = 0; p < 2; p++) {
        int i = t + p * 256;
        float4 a = a4[i], hh = h4[i];
        float4 x = make_float4(a.x + hh.x, a.y + hh.y, a.z + hh.z, a.w + hh.w);
        xv[p] = x;
        s  += x.x + x.y + x.z + x.w;
        ss += x.x * x.x + x.y * x.y + x.z * x.z + x.w * x.w;
    }
    __shared__ float rs[8], rss[8];
    #pragma unroll
    for (int o = 16; o > 0; o >>= 1) {
        s  += __shfl_xor_sync(0xffffffffu, s, o);
        ss += __shfl_xor_sync(0xffffffffu, ss, o);
    }
    if ((t & 31) == 0) { rs[t >> 5] = s; rss[t >> 5] = ss; }
    __syncthreads();
    float ts = 0.0f, tss = 0.0f;
    #pragma unroll
    for (int i = 0; i < 8; i++) { ts += rs[i]; tss += rss[i]; }
    const float mean = ts * (1.0f / Hd);
    const float var  = tss * (1.0f / Hd) - mean * mean;
    const float inv  = rsqrtf(var + 1e-5f);

    const float4* g4 = (const float4*)gamma;
    const float4* b4 = (const float4*)beta;
    float4* o4 = (float4*)(out + (size_t)row * Hd);
    #pragma unroll
    for (int p = 0; p < 2; p++) {
        int i = t + p * 256;
        float4 gv = g4[i], bv = b4[i], x = xv[p];
        o4[i] = make_float4((x.x - mean) * inv * gv.x + bv.x,
                            (x.y - mean) * inv * gv.y + bv.y,
                            (x.z - mean) * inv * gv.z + bv.z,
                            (x.w - mean) * inv * gv.w + bv.w);
    }
}

// =====================================================================
// launcher
// =====================================================================
extern "C" void kernel_launch(void* const* d_in, const int* in_sizes, int n_in,
                              void* d_out, int out_size)
{
    const float* hidden = (const float*)d_in[0];
    const float* audio  = (const float*)d_in[1];
    const float* amask  = (const float*)d_in[2];
    const float* Wq = (const float*)d_in[3];
    const float* bq = (const float*)d_in[4];
    const float* Wk = (const float*)d_in[5];
    const float* bk = (const float*)d_in[6];
    const float* Wv = (const float*)d_in[7];
    const float* bv = (const float*)d_in[8];
    const float* Wo = (const float*)d_in[9];
    const float* bo = (const float*)d_in[10];
    const float* gamma = (const float*)d_in[11];
    const float* beta  = (const float*)d_in[12];
    float* out = (float*)d_out;

    __half *hidh, *audh, *Wh, *Qh, *Kh, *Vh, *ctxh;
    float* attp;
    cudaGetSymbolAddress((void**)&hidh, g_hidh);
    cudaGetSymbolAddress((void**)&audh, g_audh);
    cudaGetSymbolAddress((void**)&Wh,   g_Wh);
    cudaGetSymbolAddress((void**)&Qh,   g_Qh);
    cudaGetSymbolAddress((void**)&Kh,   g_Kh);
    cudaGetSymbolAddress((void**)&Vh,   g_Vh);
    cudaGetSymbolAddress((void**)&ctxh, g_ctxh);
    cudaGetSymbolAddress((void**)&attp, g_att);
    __half* WqT = Wh;
    __half* WkT = Wh + (size_t)Hd * Hd;
    __half* WvT = Wh + 2 * (size_t)Hd * Hd;
    __half* WoT = Wh + 3 * (size_t)Hd * Hd;

    cudaFuncSetAttribute(attn_kernel, cudaFuncAttributeMaxDynamicSharedMemorySize,
                         ATTN_SMEM_BYTES);

    f2h_kernel<<<(Bd * Sd * Hd) / 1024, 256>>>(hidden, hidh);
    f2h_kernel<<<(Bd * Ad * Hd) / 1024, 256>>>(audio, audh);
    dim3 tg(Hd / 32, Hd / 32), tb(32, 8);
    transpose_h_kernel<<<tg, tb>>>(Wq, WqT);
    transpose_h_kernel<<<tg, tb>>>(Wk, WkT);
    transpose_h_kernel<<<tg, tb>>>(Wv, WvT);
    transpose_h_kernel<<<tg, tb>>>(Wo, WoT);

    gemm_h_kernel<true><<<dim3(16, (Bd * Sd) / 128), 256>>>(hidh, WqT, bq, Qh);
    gemm_h_kernel<true><<<dim3(16, (Bd * Ad) / 128), 256>>>(audh, WkT, bk, Kh);
    gemm_h_kernel<true><<<dim3(16, (Bd * Ad) / 128), 256>>>(audh, WvT, bv, Vh);
    attn_kernel<<<Bd * NHd * (Sd / 64), 256, ATTN_SMEM_BYTES>>>(amask);
    gemm_h_kernel<false><<<dim3(16, (Bd * Sd) / 128), 256>>>(ctxh, WoT, bo, attp);
    ln_kernel<<<Bd * Sd, 256>>>(attp, hidden, gamma, beta, out);
}

// round 13
// speedup vs baseline: 2.0589x; 1.0701x over previous
#include <cuda_runtime.h>
#include <cuda_fp16.h>
#include <cstdint>

#define Hd   2048
#define NHd  16
#define DHd  128
#define Bd   4
#define Sd   2048
#define Ad   512

// ---------------- scratch (static device arrays; no allocation) ----------------
__device__ __half g_hidh[(size_t)Bd * Sd * Hd];
__device__ __half g_audh[(size_t)Bd * Ad * Hd];
__device__ __half g_Wh[4][(size_t)Hd * Hd];       // transposed fp16 weights [n][k]
__device__ __half g_Qh[(size_t)Bd * Sd * Hd];
__device__ __half g_Kh[(size_t)Bd * Ad * Hd];
__device__ __half g_Vh[(size_t)Bd * Ad * Hd];
__device__ __half g_ctxh[(size_t)Bd * Sd * Hd];
__device__ float  g_att[(size_t)Bd * Sd * Hd];

// ---------------- helpers ----------------
__device__ __forceinline__ void cp16(void* dst, const void* src) {
    uint32_t d = (uint32_t)__cvta_generic_to_shared(dst);
    asm volatile("cp.async.cg.shared.global [%0], [%1], 16;\n" :: "r"(d), "l"(src));
}
#define CP_COMMIT asm volatile("cp.async.commit_group;\n" ::: "memory")
#define CP_WAIT0  asm volatile("cp.async.wait_group 0;\n" ::: "memory")
#define CP_WAIT1  asm volatile("cp.async.wait_group 1;\n" ::: "memory")
#define CP_WAIT2  asm volatile("cp.async.wait_group 2;\n" ::: "memory")

__device__ __forceinline__ uint32_t smaddr(const void* p) {
    return (uint32_t)__cvta_generic_to_shared(p);
}

__device__ __forceinline__ void ldm4(uint32_t r[4], uint32_t a) {
    asm volatile("ldmatrix.sync.aligned.m8n8.x4.shared.b16 {%0,%1,%2,%3}, [%4];"
                 : "=r"(r[0]), "=r"(r[1]), "=r"(r[2]), "=r"(r[3]) : "r"(a));
}
__device__ __forceinline__ void ldm4t(uint32_t r[4], uint32_t a) {
    asm volatile("ldmatrix.sync.aligned.m8n8.x4.trans.shared.b16 {%0,%1,%2,%3}, [%4];"
                 : "=r"(r[0]), "=r"(r[1]), "=r"(r[2]), "=r"(r[3]) : "r"(a));
}

__device__ __forceinline__ void mma_f16(float c[4], const uint32_t a[4], const uint32_t b[2]) {
    asm volatile(
        "mma.sync.aligned.m16n8k16.row.col.f32.f16.f16.f32 "
        "{%0,%1,%2,%3}, {%4,%5,%6,%7}, {%8,%9}, {%0,%1,%2,%3};"
        : "+f"(c[0]), "+f"(c[1]), "+f"(c[2]), "+f"(c[3])
        : "r"(a[0]), "r"(a[1]), "r"(a[2]), "r"(a[3]), "r"(b[0]), "r"(b[1]));
}

__device__ __forceinline__ uint32_t packf2(float a, float b) {
    __half2 h = __floats2half2_rn(a, b);
    return *(uint32_t*)&h;
}

// =====================================================================
// fp32 -> fp16 elementwise
// =====================================================================
__global__ void __launch_bounds__(256) f2h_kernel(
    const float* __restrict__ in, __half* __restrict__ out)
{
    int i = blockIdx.x * 256 + threadIdx.x;
    float4 v = ((const float4*)in)[i];
    __half2* o2 = (__half2*)out;
    o2[2 * i]     = __floats2half2_rn(v.x, v.y);
    o2[2 * i + 1] = __floats2half2_rn(v.z, v.w);
}

// =====================================================================
// transpose + convert: out[n][k] = (half) in[k][n]
// =====================================================================
__global__ void __launch_bounds__(256) transpose_h_kernel(
    const float* __restrict__ in, __half* __restrict__ out)
{
    __shared__ float t[32][33];
    const int bx = blockIdx.x * 32, by = blockIdx.y * 32;
    const int tx = threadIdx.x, ty = threadIdx.y;
    #pragma unroll
    for (int r = 0; r < 32; r += 8)
        t[ty + r][tx] = in[(size_t)(by + ty + r) * Hd + bx + tx];
    __syncthreads();
    #pragma unroll
    for (int r = 0; r < 32; r += 8)
        out[(size_t)(bx + ty + r) * Hd + by + tx] = __float2half_rn(t[tx][ty + r]);
}

// =====================================================================
// fp16 GEMM with ldmatrix fragment loads (unchanged from R12, at pipe ceiling).
// =====================================================================
template<bool HALF_OUT>
__global__ void __launch_bounds__(256) gemm_h_kernel(
    const __half* __restrict__ X, const __half* __restrict__ Wt,
    const float* __restrict__ bias, void* __restrict__ Cout)
{
    __shared__ __half As[2][128][40];
    __shared__ __half Bs[2][128][40];

    const int tid  = threadIdx.x;
    const int lane = tid & 31, wid = tid >> 5;
    const int g    = lane >> 2, tig = lane & 3;
    const int wm   = wid >> 2,  wn  = wid & 3;
    const int m0   = blockIdx.y * 128, n0 = blockIdx.x * 128;

    const int r_ld = tid >> 1;
    const int c_ld = (tid & 1) * 16;

    const int lm_r = (lane & 7) + ((lane >> 3) & 1) * 8;
    const int lm_c = (lane >> 4) * 8;

    float acc[4][4][4];
    #pragma unroll
    for (int mi = 0; mi < 4; mi++)
        #pragma unroll
        for (int ni = 0; ni < 4; ni++)
            #pragma unroll
            for (int j = 0; j < 4; j++) acc[mi][ni][j] = 0.0f;

    auto load_stage = [&](int st, int k0) {
        const __half* xs = X  + (size_t)(m0 + r_ld) * Hd + k0 + c_ld;
        cp16(&As[st][r_ld][c_ld],     xs);
        cp16(&As[st][r_ld][c_ld + 8], xs + 8);
        const __half* ws = Wt + (size_t)(n0 + r_ld) * Hd + k0 + c_ld;
        cp16(&Bs[st][r_ld][c_ld],     ws);
        cp16(&Bs[st][r_ld][c_ld + 8], ws + 8);
        CP_COMMIT;
    };

    load_stage(0, 0);
    int st = 0;

    #pragma unroll 1
    for (int k0 = 0; k0 < Hd; k0 += 32) {
        CP_WAIT0;
        __syncthreads();
        if (k0 + 32 < Hd) load_stage(st ^ 1, k0 + 32);

        #pragma unroll
        for (int kk = 0; kk < 32; kk += 16) {
            uint32_t af[4][4];
            #pragma unroll
            for (int mi = 0; mi < 4; mi++)
                ldm4(af[mi], smaddr(&As[st][wm * 64 + mi * 16 + lm_r][kk + lm_c]));
            uint32_t bf[4][2];
            #pragma unroll
            for (int nb = 0; nb < 2; nb++) {
                uint32_t t4[4];
                int nrow = wn * 32 + nb * 16 + (lane & 7) + (lane >> 4) * 8;
                int ncol = kk + ((lane >> 3) & 1) * 8;
                ldm4(t4, smaddr(&Bs[st][nrow][ncol]));
                bf[2 * nb][0]     = t4[0];
                bf[2 * nb][1]     = t4[1];
                bf[2 * nb + 1][0] = t4[2];
                bf[2 * nb + 1][1] = t4[3];
            }
            #pragma unroll
            for (int mi = 0; mi < 4; mi++)
                #pragma unroll
                for (int ni = 0; ni < 4; ni++)
                    mma_f16(acc[mi][ni], af[mi], bf[ni]);
        }
        st ^= 1;
    }

    #pragma unroll
    for (int mi = 0; mi < 4; mi++) {
        #pragma unroll
        for (int ni = 0; ni < 4; ni++) {
            int r = m0 + wm * 64 + mi * 16 + g;
            int c = n0 + wn * 32 + ni * 8 + tig * 2;
            float b0 = bias[c], b1 = bias[c + 1];
            if (HALF_OUT) {
                __half* C = (__half*)Cout;
                *(__half2*)(C + (size_t)r * Hd + c) =
                    __floats2half2_rn(acc[mi][ni][0] + b0, acc[mi][ni][1] + b1);
                *(__half2*)(C + (size_t)(r + 8) * Hd + c) =
                    __floats2half2_rn(acc[mi][ni][2] + b0, acc[mi][ni][3] + b1);
            } else {
                float* C = (float*)Cout;
                *(float2*)(C + (size_t)r * Hd + c) =
                    make_float2(acc[mi][ni][0] + b0, acc[mi][ni][1] + b1);
                *(float2*)(C + (size_t)(r + 8) * Hd + c) =
                    make_float2(acc[mi][ni][2] + b0, acc[mi][ni][3] + b1);
            }
        }
    }
}

// =====================================================================
// Flash attention: CTA = 64 q-rows x one head; 128 threads, 4 warps,
// warp = 16 q-rows x full kv width. Online softmax, no score buffer.
// smem: Qs 64x136h + K[2] 64x136h + V[2] 64x136h + mv 512f = 89,088 B
// =====================================================================
#define AT_Q   0
#define AT_K   17408
#define AT_V   52224
#define AT_MV  87040
#define ATTN_SMEM_BYTES 89088

__global__ void __launch_bounds__(128) attn_kernel(const float* __restrict__ mask)
{
    extern __shared__ char smc[];
    __half (*Qs)[136] = (__half (*)[136])(smc + AT_Q);
    float* mv = (float*)(smc + AT_MV);

    const int tid  = threadIdx.x;
    const int lane = tid & 31, wid = tid >> 5;       // 4 warps
    const int g    = lane >> 2, tig = lane & 3;

    const int bx = blockIdx.x;
    const int qt = bx & 31;
    const int h  = (bx >> 5) & 15;
    const int b  = bx >> 9;
    const int qrow0 = b * Sd + qt * 64;
    const int krow0 = b * Ad;
    const int hoff  = h * DHd;
    const float scale = 0.0883883476483184f;         // 1/sqrt(128)

    // 64x128-half tile = 1024 cp16; 128 threads -> 8 each
    auto load_tile = [&](char* dstbase, const __half* src_base) {
        __half (*dst)[136] = (__half (*)[136])dstbase;
        #pragma unroll
        for (int p = 0; p < 8; p++) {
            int i = tid + p * 128;
            int r = i >> 4, c = (i & 15) * 8;
            cp16(&dst[r][c], src_base + (size_t)r * Hd + c);
        }
        CP_COMMIT;
    };
    auto Kst = [&](int st) { return smc + AT_K + st * 17408; };
    auto Vst = [&](int st) { return smc + AT_V + st * 17408; };

    // prologue: Q | KV0 | KV1 as three commit groups
    load_tile(smc + AT_Q, g_Qh + (size_t)qrow0 * Hd + hoff);
    {
        load_tile(Kst(0), g_Kh + (size_t)krow0 * Hd + hoff);   // commit (K0)
        // merge V0 into same group as K0: re-commit below covers both? No:
    }
    // NOTE: load_tile commits internally; K and V of a chunk form 2 groups.
    load_tile(Vst(0), g_Vh + (size_t)krow0 * Hd + hoff);
    load_tile(Kst(1), g_Kh + (size_t)(krow0 + 64) * Hd + hoff);
    load_tile(Vst(1), g_Vh + (size_t)(krow0 + 64) * Hd + hoff);
    #pragma unroll
    for (int p = 0; p < 4; p++) {
        int i = tid + p * 128;
        mv[i] = mask[b * Ad + i] * -10000.0f;
    }

    // wait for Q (4 groups in flight; leave newest 4-1=... Q is oldest of 5? groups: Q,K0,V0,K1,V1)
    asm volatile("cp.async.wait_group 4;\n" ::: "memory");
    __syncthreads();

    // Q fragments, loaded once
    const int lm_r = (lane & 7) + ((lane >> 3) & 1) * 8;
    const int lm_c = (lane >> 4) * 8;
    uint32_t qf[8][4];
    #pragma unroll
    for (int kk = 0; kk < 8; kk++)
        ldm4(qf[kk], smaddr(&Qs[wid * 16 + lm_r][kk * 16 + lm_c]));

    float oacc[16][4];
    #pragma unroll
    for (int ni = 0; ni < 16; ni++)
        #pragma unroll
        for (int j = 0; j < 4; j++) oacc[ni][j] = 0.0f;
    float m0 = -1e30f, m1 = -1e30f, l0 = 0.0f, l1 = 0.0f;

    // K ldmatrix lane geometry (non-trans): rows = n, cols = k
    const int kq_r = (lane & 7) + (lane >> 4) * 8;
    const int kq_c = ((lane >> 3) & 1) * 8;
    // V ldmatrix lane geometry (trans): rows = k, cols = n
    const int vt_r = (lane & 7) + ((lane >> 3) & 1) * 8;
    const int vt_c = (lane >> 4) * 8;

    #pragma unroll 1
    for (int c = 0; c < 8; c++) {
        const int st = c & 1;
        // groups pending before wait: K_c,V_c,K_{c+1},V_{c+1} (or fewer at tail)
        if (c < 6) { CP_WAIT2; } else { CP_WAIT0; }
        __syncthreads();
        const __half (*Kb)[136] = (const __half (*)[136])Kst(st);
        const __half (*Vb)[136] = (const __half (*)[136])Vst(st);

        // ---- S = Q K^T : 16 x 64 per warp ----
        float sacc[8][4];
        #pragma unroll
        for (int ni = 0; ni < 8; ni++)
            #pragma unroll
            for (int j = 0; j < 4; j++) sacc[ni][j] = 0.0f;

        #pragma unroll
        for (int kk = 0; kk < 8; kk++) {
            uint32_t bf[8][2];
            #pragma unroll
            for (int nb = 0; nb < 4; nb++) {
                uint32_t t4[4];
                ldm4(t4, smaddr(&Kb[nb * 16 + kq_r][kk * 16 + kq_c]));
                bf[2 * nb][0]     = t4[0];
                bf[2 * nb][1]     = t4[1];
                bf[2 * nb + 1][0] = t4[2];
                bf[2 * nb + 1][1] = t4[3];
            }
            #pragma unroll
            for (int ni = 0; ni < 8; ni++)
                mma_f16(sacc[ni], qf[kk], bf[ni]);
        }

        // ---- online softmax (rows g and g+8 of this warp's 16) ----
        const int cb = c * 64;
        float p[8][4];
        float rmax0 = -1e30f, rmax1 = -1e30f;
        #pragma unroll
        for (int ni = 0; ni < 8; ni++) {
            float mva = mv[cb + ni * 8 + 2 * tig];
            float mvb = mv[cb + ni * 8 + 2 * tig + 1];
            p[ni][0] = sacc[ni][0] * scale + mva;
            p[ni][1] = sacc[ni][1] * scale + mvb;
            p[ni][2] = sacc[ni][2] * scale + mva;
            p[ni][3] = sacc[ni][3] * scale + mvb;
            rmax0 = fmaxf(rmax0, fmaxf(p[ni][0], p[ni][1]));
            rmax1 = fmaxf(rmax1, fmaxf(p[ni][2], p[ni][3]));
        }
        rmax0 = fmaxf(rmax0, __shfl_xor_sync(0xffffffffu, rmax0, 1));
        rmax0 = fmaxf(rmax0, __shfl_xor_sync(0xffffffffu, rmax0, 2));
        rmax1 = fmaxf(rmax1, __shfl_xor_sync(0xffffffffu, rmax1, 1));
        rmax1 = fmaxf(rmax1, __shfl_xor_sync(0xffffffffu, rmax1, 2));
        float m0n = fmaxf(m0, rmax0), m1n = fmaxf(m1, rmax1);
        float cr0 = __expf(m0 - m0n), cr1 = __expf(m1 - m1n);
        float rs0 = 0.0f, rs1 = 0.0f;
        #pragma unroll
        for (int ni = 0; ni < 8; ni++) {
            p[ni][0] = __expf(p[ni][0] - m0n);
            p[ni][1] = __expf(p[ni][1] - m0n);
            p[ni][2] = __expf(p[ni][2] - m1n);
            p[ni][3] = __expf(p[ni][3] - m1n);
            rs0 += p[ni][0] + p[ni][1];
            rs1 += p[ni][2] + p[ni][3];
        }
        rs0 += __shfl_xor_sync(0xffffffffu, rs0, 1);
        rs0 += __shfl_xor_sync(0xffffffffu, rs0, 2);
        rs1 += __shfl_xor_sync(0xffffffffu, rs1, 1);
        rs1 += __shfl_xor_sync(0xffffffffu, rs1, 2);
        l0 = l0 * cr0 + rs0;  m0 = m0n;
        l1 = l1 * cr1 + rs1;  m1 = m1n;
        #pragma unroll
        for (int ni = 0; ni < 16; ni++) {
            oacc[ni][0] *= cr0; oacc[ni][1] *= cr0;
            oacc[ni][2] *= cr1; oacc[ni][3] *= cr1;
        }
        // P a-frags straight from registers
        uint32_t pf[4][4];
        #pragma unroll
        for (int t = 0; t < 4; t++) {
            pf[t][0] = packf2(p[2 * t][0],     p[2 * t][1]);
            pf[t][1] = packf2(p[2 * t][2],     p[2 * t][3]);
            pf[t][2] = packf2(p[2 * t + 1][0], p[2 * t + 1][1]);
            pf[t][3] = packf2(p[2 * t + 1][2], p[2 * t + 1][3]);
        }

        // ---- O += P V : 16 x 128 per warp ----
        #pragma unroll
        for (int t = 0; t < 4; t++) {
            #pragma unroll
            for (int nb = 0; nb < 8; nb++) {
                uint32_t t4[4];
                ldm4t(t4, smaddr(&Vb[t * 16 + vt_r][nb * 16 + vt_c]));
                mma_f16(oacc[2 * nb],     pf[t], t4);       // uses t4[0..1]
                mma_f16(oacc[2 * nb + 1], pf[t], t4 + 2);   // uses t4[2..3]
            }
        }

        __syncthreads();   // all reads of stage st done before refill
        if (c + 2 < 8) {
            load_tile(Kst(st), g_Kh + (size_t)(krow0 + (c + 2) * 64) * Hd + hoff);
            load_tile(Vst(st), g_Vh + (size_t)(krow0 + (c + 2) * 64) * Hd + hoff);
        }
    }

    // ---- epilogue ----
    float i0 = 1.0f / l0, i1 = 1.0f / l1;
    const int row = qrow0 + wid * 16 + g;
    #pragma unroll
    for (int ni = 0; ni < 16; ni++) {
        int col = hoff + ni * 8 + 2 * tig;
        *(__half2*)(g_ctxh + (size_t)row * Hd + col) =
            __floats2half2_rn(oacc[ni][0] * i0, oacc[ni][1] * i0);
        *(__half2*)(g_ctxh + (size_t)(row + 8) * Hd + col) =
            __floats2half2_rn(oacc[ni][2] * i1, oacc[ni][3] * i1);
    }
}

// =====================================================================
// Residual + LayerNorm
// =====================================================================
__global__ void __launch_bounds__(256) ln_kernel(
    const float* __restrict__ att, const float* __restrict__ hid,
    const float* __restrict__ gamma, const float* __restrict__ beta,
    float* __restrict__ out)
{
    const int row = blockIdx.x, t = threadIdx.x;
    const float4* a4 = (const float4*)(att + (size_t)row * Hd);
    const float4* h4 = (const float4*)(hid + (size_t)row * Hd);

    float4 xv[2];
    float s = 0.0f, ss = 0.0f;
    #pragma unroll
    for (int p = 0; p < 2; p++) {
        int i = t + p * 256;
        float4 a = a4[i], hh = h4[i];
        float4 x = make_float4(a.x + hh.x, a.y + hh.y, a.z + hh.z, a.w + hh.w);
        xv[p] = x;
        s  += x.x + x.y + x.z + x.w;
        ss += x.x * x.x + x.y * x.y + x.z * x.z + x.w * x.w;
    }
    __shared__ float rs[8], rss[8];
    #pragma unroll
    for (int o = 16; o > 0; o >>= 1) {
        s  += __shfl_xor_sync(0xffffffffu, s, o);
        ss += __shfl_xor_sync(0xffffffffu, ss, o);
    }
    if ((t & 31) == 0) { rs[t >> 5] = s; rss[t >> 5] = ss; }
    __syncthreads();
    float ts = 0.0f, tss = 0.0f;
    #pragma unroll
    for (int i = 0; i < 8; i++) { ts += rs[i]; tss += rss[i]; }
    const float mean = ts * (1.0f / Hd);
    const float var  = tss * (1.0f / Hd) - mean * mean;
    const float inv  = rsqrtf(var + 1e-5f);

    const float4* g4 = (const float4*)gamma;
    const float4* b4 = (const float4*)beta;
    float4* o4 = (float4*)(out + (size_t)row * Hd);
    #pragma unroll
    for (int p = 0; p < 2; p++) {
        int i = t + p * 256;
        float4 gv = g4[i], bv = b4[i], x = xv[p];
        o4[i] = make_float4((x.x - mean) * inv * gv.x + bv.x,
                            (x.y - mean) * inv * gv.y + bv.y,
                            (x.z - mean) * inv * gv.z + bv.z,
                            (x.w - mean) * inv * gv.w + bv.w);
    }
}

// =====================================================================
// launcher
// =====================================================================
extern "C" void kernel_launch(void* const* d_in, const int* in_sizes, int n_in,
                              void* d_out, int out_size)
{
    const float* hidden = (const float*)d_in[0];
    const float* audio  = (const float*)d_in[1];
    const float* amask  = (const float*)d_in[2];
    const float* Wq = (const float*)d_in[3];
    const float* bq = (const float*)d_in[4];
    const float* Wk = (const float*)d_in[5];
    const float* bk = (const float*)d_in[6];
    const float* Wv = (const float*)d_in[7];
    const float* bv = (const float*)d_in[8];
    const float* Wo = (const float*)d_in[9];
    const float* bo = (const float*)d_in[10];
    const float* gamma = (const float*)d_in[11];
    const float* beta  = (const float*)d_in[12];
    float* out = (float*)d_out;

    __half *hidh, *audh, *Wh, *Qh, *Kh, *Vh, *ctxh;
    float* attp;
    cudaGetSymbolAddress((void**)&hidh, g_hidh);
    cudaGetSymbolAddress((void**)&audh, g_audh);
    cudaGetSymbolAddress((void**)&Wh,   g_Wh);
    cudaGetSymbolAddress((void**)&Qh,   g_Qh);
    cudaGetSymbolAddress((void**)&Kh,   g_Kh);
    cudaGetSymbolAddress((void**)&Vh,   g_Vh);
    cudaGetSymbolAddress((void**)&ctxh, g_ctxh);
    cudaGetSymbolAddress((void**)&attp, g_att);
    __half* WqT = Wh;
    __half* WkT = Wh + (size_t)Hd * Hd;
    __half* WvT = Wh + 2 * (size_t)Hd * Hd;
    __half* WoT = Wh + 3 * (size_t)Hd * Hd;

    cudaFuncSetAttribute(attn_kernel, cudaFuncAttributeMaxDynamicSharedMemorySize,
                         ATTN_SMEM_BYTES);

    f2h_kernel<<<(Bd * Sd * Hd) / 1024, 256>>>(hidden, hidh);
    f2h_kernel<<<(Bd * Ad * Hd) / 1024, 256>>>(audio, audh);
    dim3 tg(Hd / 32, Hd / 32), tb(32, 8);
    transpose_h_kernel<<<tg, tb>>>(Wq, WqT);
    transpose_h_kernel<<<tg, tb>>>(Wk, WkT);
    transpose_h_kernel<<<tg, tb>>>(Wv, WvT);
    transpose_h_kernel<<<tg, tb>>>(Wo, WoT);

    gemm_h_kernel<true><<<dim3(16, (Bd * Sd) / 128), 256>>>(hidh, WqT, bq, Qh);
    gemm_h_kernel<true><<<dim3(16, (Bd * Ad) / 128), 256>>>(audh, WkT, bk, Kh);
    gemm_h_kernel<true><<<dim3(16, (Bd * Ad) / 128), 256>>>(audh, WvT, bv, Vh);
    attn_kernel<<<Bd * NHd * (Sd / 64), 128, ATTN_SMEM_BYTES>>>(amask);
    gemm_h_kernel<false><<<dim3(16, (Bd * Sd) / 128), 256>>>(ctxh, WoT, bo, attp);
    ln_kernel<<<Bd * Sd, 256>>>(attp, hidden, gamma, beta, out);
}

// round 14
// speedup vs baseline: 2.3264x; 1.1299x over previous
#include <cuda_runtime.h>
#include <cuda_fp16.h>
#include <cstdint>

#define Hd   2048
#define NHd  16
#define DHd  128
#define Bd   4
#define Sd   2048
#define Ad   512

// ---------------- scratch (static device arrays; no allocation) ----------------
__device__ __half g_hidh[(size_t)Bd * Sd * Hd];
__device__ __half g_audh[(size_t)Bd * Ad * Hd];
__device__ __half g_Wh[4][(size_t)Hd * Hd];       // fp16 weights, natural [k][n] layout
__device__ __half g_Qh[(size_t)Bd * Sd * Hd];
__device__ __half g_Kh[(size_t)Bd * Ad * Hd];
__device__ __half g_Vh[(size_t)Bd * Ad * Hd];
__device__ __half g_ctxh[(size_t)Bd * Sd * Hd];
__device__ float  g_att[(size_t)Bd * Sd * Hd];    // out_proj + residual (fp32)

// ---------------- helpers ----------------
__device__ __forceinline__ void cp16(void* dst, const void* src) {
    uint32_t d = (uint32_t)__cvta_generic_to_shared(dst);
    asm volatile("cp.async.cg.shared.global [%0], [%1], 16;\n" :: "r"(d), "l"(src));
}
#define CP_COMMIT asm volatile("cp.async.commit_group;\n" ::: "memory")
#define CP_WAIT0  asm volatile("cp.async.wait_group 0;\n" ::: "memory")
#define CP_WAIT1  asm volatile("cp.async.wait_group 1;\n" ::: "memory")
#define CP_WAIT2  asm volatile("cp.async.wait_group 2;\n" ::: "memory")

__device__ __forceinline__ uint32_t smaddr(const void* p) {
    return (uint32_t)__cvta_generic_to_shared(p);
}

__device__ __forceinline__ void ldm4(uint32_t r[4], uint32_t a) {
    asm volatile("ldmatrix.sync.aligned.m8n8.x4.shared.b16 {%0,%1,%2,%3}, [%4];"
                 : "=r"(r[0]), "=r"(r[1]), "=r"(r[2]), "=r"(r[3]) : "r"(a));
}
__device__ __forceinline__ void ldm4t(uint32_t r[4], uint32_t a) {
    asm volatile("ldmatrix.sync.aligned.m8n8.x4.trans.shared.b16 {%0,%1,%2,%3}, [%4];"
                 : "=r"(r[0]), "=r"(r[1]), "=r"(r[2]), "=r"(r[3]) : "r"(a));
}

__device__ __forceinline__ void mma_f16(float c[4], const uint32_t a[4], const uint32_t b[2]) {
    asm volatile(
        "mma.sync.aligned.m16n8k16.row.col.f32.f16.f16.f32 "
        "{%0,%1,%2,%3}, {%4,%5,%6,%7}, {%8,%9}, {%0,%1,%2,%3};"
        : "+f"(c[0]), "+f"(c[1]), "+f"(c[2]), "+f"(c[3])
        : "r"(a[0]), "r"(a[1]), "r"(a[2]), "r"(a[3]), "r"(b[0]), "r"(b[1]));
}

__device__ __forceinline__ uint32_t packf2(float a, float b) {
    __half2 h = __floats2half2_rn(a, b);
    return *(uint32_t*)&h;
}

// =====================================================================
// fp32 -> fp16 elementwise
// =====================================================================
__global__ void __launch_bounds__(256) f2h_kernel(
    const float* __restrict__ in, __half* __restrict__ out)
{
    int i = blockIdx.x * 256 + threadIdx.x;
    float4 v = ((const float4*)in)[i];
    __half2* o2 = (__half2*)out;
    o2[2 * i]     = __floats2half2_rn(v.x, v.y);
    o2[2 * i + 1] = __floats2half2_rn(v.z, v.w);
}

// =====================================================================
// fp16 GEMM: C[M x 2048] = X[M x 2048] @ W + bias (+ optional fp32 residual)
//   X fp16 [m][k]; W fp16 [k][n] natural layout (B-frags via ldmatrix.trans).
//   128x128 tile, BK=32, 256 threads (8 warps 2x4, warp tile 64x32),
//   3-stage cp.async pipeline, dynamic smem.
// =====================================================================
#define GEMM_SMEM_BYTES (3 * 128 * 40 * 2 + 3 * 32 * 136 * 2)   // 30720 + 26112 = 56832

template<bool HALF_OUT, bool RES>
__global__ void __launch_bounds__(256) gemm_h_kernel(
    const __half* __restrict__ X, const __half* __restrict__ W,
    const float* __restrict__ bias, const float* __restrict__ res,
    void* __restrict__ Cout)
{
    extern __shared__ char gsm[];
    __half (*As)[128][40] = (__half (*)[128][40])gsm;             // [3][128][40]
    __half (*Bs)[32][136] = (__half (*)[32][136])(gsm + 30720);   // [3][32][136]

    const int tid  = threadIdx.x;
    const int lane = tid & 31, wid = tid >> 5;
    const int g    = lane >> 2, tig = lane & 3;
    const int wm   = wid >> 2,  wn  = wid & 3;
    const int m0   = blockIdx.y * 128, n0 = blockIdx.x * 128;

    // A tile loaders: 128 rows x 32 cols
    const int ar = tid >> 1;
    const int ac = (tid & 1) * 16;
    // B tile loaders: 32 k-rows x 128 n-cols
    const int brow = tid >> 3;
    const int bcol = (tid & 7) * 8;

    // ldmatrix geometry
    const int lm_r = (lane & 7) + ((lane >> 3) & 1) * 8;   // A (non-trans)
    const int lm_c = (lane >> 4) * 8;
    const int vt_r = (lane & 7) + ((lane >> 3) & 1) * 8;   // B (trans): rows = k
    const int vt_c = (lane >> 4) * 8;                      //            cols = n

    float acc[4][4][4];
    #pragma unroll
    for (int mi = 0; mi < 4; mi++)
        #pragma unroll
        for (int ni = 0; ni < 4; ni++)
            #pragma unroll
            for (int j = 0; j < 4; j++) acc[mi][ni][j] = 0.0f;

    auto load_stage = [&](int st, int k0) {
        const __half* xs = X + (size_t)(m0 + ar) * Hd + k0 + ac;
        cp16(&As[st][ar][ac],     xs);
        cp16(&As[st][ar][ac + 8], xs + 8);
        const __half* ws = W + (size_t)(k0 + brow) * Hd + n0 + bcol;
        cp16(&Bs[st][brow][bcol],      ws);
        cp16(&Bs[st][brow][bcol + 64], ws + 64);
        CP_COMMIT;
    };

    load_stage(0, 0);
    load_stage(1, 32);

    #pragma unroll 1
    for (int c = 0; c < Hd / 32; c++) {
        const int st = c % 3;
        CP_WAIT1;            // chunk c arrived (c+1 may still be in flight)
        __syncthreads();     // also guards buffer (c+2)%3 reuse (compute c-1 done)
        if (c + 2 < Hd / 32) load_stage((c + 2) % 3, (c + 2) * 32);

        #pragma unroll
        for (int kk = 0; kk < 32; kk += 16) {
            uint32_t af[4][4];
            #pragma unroll
            for (int mi = 0; mi < 4; mi++)
                ldm4(af[mi], smaddr(&As[st][wm * 64 + mi * 16 + lm_r][kk + lm_c]));
            uint32_t bf[4][2];
            #pragma unroll
            for (int nb = 0; nb < 2; nb++) {
                uint32_t t4[4];
                ldm4t(t4, smaddr(&Bs[st][kk + vt_r][wn * 32 + nb * 16 + vt_c]));
                bf[2 * nb][0]     = t4[0];
                bf[2 * nb][1]     = t4[1];
                bf[2 * nb + 1][0] = t4[2];
                bf[2 * nb + 1][1] = t4[3];
            }
            #pragma unroll
            for (int mi = 0; mi < 4; mi++)
                #pragma unroll
                for (int ni = 0; ni < 4; ni++)
                    mma_f16(acc[mi][ni], af[mi], bf[ni]);
        }
    }

    #pragma unroll
    for (int mi = 0; mi < 4; mi++) {
        #pragma unroll
        for (int ni = 0; ni < 4; ni++) {
            int r = m0 + wm * 64 + mi * 16 + g;
            int c = n0 + wn * 32 + ni * 8 + tig * 2;
            float v0 = acc[mi][ni][0] + bias[c];
            float v1 = acc[mi][ni][1] + bias[c + 1];
            float v2 = acc[mi][ni][2] + bias[c];
            float v3 = acc[mi][ni][3] + bias[c + 1];
            if (RES) {
                float2 r0 = *(const float2*)(res + (size_t)r * Hd + c);
                float2 r1 = *(const float2*)(res + (size_t)(r + 8) * Hd + c);
                v0 += r0.x; v1 += r0.y; v2 += r1.x; v3 += r1.y;
            }
            if (HALF_OUT) {
                __half* C = (__half*)Cout;
                *(__half2*)(C + (size_t)r * Hd + c)       = __floats2half2_rn(v0, v1);
                *(__half2*)(C + (size_t)(r + 8) * Hd + c) = __floats2half2_rn(v2, v3);
            } else {
                float* C = (float*)Cout;
                *(float2*)(C + (size_t)r * Hd + c)       = make_float2(v0, v1);
                *(float2*)(C + (size_t)(r + 8) * Hd + c) = make_float2(v2, v3);
            }
        }
    }
}

// =====================================================================
// Flash attention: CTA = 64 q-rows x one head; 128 threads, 4 warps.
// Q fragments loaded once from gmem (no Q smem tile).
// smem: K[2] 64x136h + V[2] 64x136h + mv 512f = 71,680 B -> 3 CTAs/SM
// =====================================================================
#define AT_K   0
#define AT_V   34816
#define AT_MV  69632
#define ATTN_SMEM_BYTES 71680

__global__ void __launch_bounds__(128) attn_kernel(const float* __restrict__ mask)
{
    extern __shared__ char smc[];
    float* mv = (float*)(smc + AT_MV);

    const int tid  = threadIdx.x;
    const int lane = tid & 31, wid = tid >> 5;       // 4 warps
    const int g    = lane >> 2, tig = lane & 3;

    const int bx = blockIdx.x;
    const int qt = bx & 31;
    const int h  = (bx >> 5) & 15;
    const int b  = bx >> 9;
    const int qrow0 = b * Sd + qt * 64;
    const int krow0 = b * Ad;
    const int hoff  = h * DHd;
    const float scale = 0.0883883476483184f;         // 1/sqrt(128)

    auto load_tile = [&](char* dstbase, const __half* src_base) {
        __half (*dst)[136] = (__half (*)[136])dstbase;
        #pragma unroll
        for (int p = 0; p < 8; p++) {
            int i = tid + p * 128;
            int r = i >> 4, c = (i & 15) * 8;
            cp16(&dst[r][c], src_base + (size_t)r * Hd + c);
        }
        CP_COMMIT;
    };
    auto Kst = [&](int st) { return smc + AT_K + st * 17408; };
    auto Vst = [&](int st) { return smc + AT_V + st * 17408; };

    // prologue: 4 commit groups K0,V0,K1,V1
    load_tile(Kst(0), g_Kh + (size_t)krow0 * Hd + hoff);
    load_tile(Vst(0), g_Vh + (size_t)krow0 * Hd + hoff);
    load_tile(Kst(1), g_Kh + (size_t)(krow0 + 64) * Hd + hoff);
    load_tile(Vst(1), g_Vh + (size_t)(krow0 + 64) * Hd + hoff);
    #pragma unroll
    for (int p = 0; p < 4; p++) {
        int i = tid + p * 128;
        mv[i] = mask[b * Ad + i] * -10000.0f;
    }

    // Q fragments direct from gmem (frag layout: rows {g, g+8}, cols {2tig, 2tig+8})
    uint32_t qf[8][4];
    {
        const __half* q0 = g_Qh + (size_t)(qrow0 + wid * 16 + g) * Hd + hoff;
        const __half* q1 = q0 + 8 * Hd;
        #pragma unroll
        for (int kk = 0; kk < 8; kk++) {
            qf[kk][0] = *(const uint32_t*)(q0 + kk * 16 + 2 * tig);
            qf[kk][1] = *(const uint32_t*)(q1 + kk * 16 + 2 * tig);
            qf[kk][2] = *(const uint32_t*)(q0 + kk * 16 + 2 * tig + 8);
            qf[kk][3] = *(const uint32_t*)(q1 + kk * 16 + 2 * tig + 8);
        }
    }

    float oacc[16][4];
    #pragma unroll
    for (int ni = 0; ni < 16; ni++)
        #pragma unroll
        for (int j = 0; j < 4; j++) oacc[ni][j] = 0.0f;
    float m0 = -1e30f, m1 = -1e30f, l0 = 0.0f, l1 = 0.0f;

    const int kq_r = (lane & 7) + (lane >> 4) * 8;     // K (non-trans): rows = n
    const int kq_c = ((lane >> 3) & 1) * 8;
    const int vt_r = (lane & 7) + ((lane >> 3) & 1) * 8;  // V (trans): rows = k
    const int vt_c = (lane >> 4) * 8;

    #pragma unroll 1
    for (int c = 0; c < 8; c++) {
        const int st = c & 1;
        if (c < 6) { CP_WAIT2; } else { CP_WAIT0; }
        __syncthreads();
        const __half (*Kb)[136] = (const __half (*)[136])Kst(st);
        const __half (*Vb)[136] = (const __half (*)[136])Vst(st);

        // ---- S = Q K^T : 16 x 64 per warp ----
        float sacc[8][4];
        #pragma unroll
        for (int ni = 0; ni < 8; ni++)
            #pragma unroll
            for (int j = 0; j < 4; j++) sacc[ni][j] = 0.0f;

        #pragma unroll
        for (int kk = 0; kk < 8; kk++) {
            uint32_t bf[8][2];
            #pragma unroll
            for (int nb = 0; nb < 4; nb++) {
                uint32_t t4[4];
                ldm4(t4, smaddr(&Kb[nb * 16 + kq_r][kk * 16 + kq_c]));
                bf[2 * nb][0]     = t4[0];
                bf[2 * nb][1]     = t4[1];
                bf[2 * nb + 1][0] = t4[2];
                bf[2 * nb + 1][1] = t4[3];
            }
            #pragma unroll
            for (int ni = 0; ni < 8; ni++)
                mma_f16(sacc[ni], qf[kk], bf[ni]);
        }

        // ---- online softmax ----
        const int cb = c * 64;
        float p[8][4];
        float rmax0 = -1e30f, rmax1 = -1e30f;
        #pragma unroll
        for (int ni = 0; ni < 8; ni++) {
            float mva = mv[cb + ni * 8 + 2 * tig];
            float mvb = mv[cb + ni * 8 + 2 * tig + 1];
            p[ni][0] = sacc[ni][0] * scale + mva;
            p[ni][1] = sacc[ni][1] * scale + mvb;
            p[ni][2] = sacc[ni][2] * scale + mva;
            p[ni][3] = sacc[ni][3] * scale + mvb;
            rmax0 = fmaxf(rmax0, fmaxf(p[ni][0], p[ni][1]));
            rmax1 = fmaxf(rmax1, fmaxf(p[ni][2], p[ni][3]));
        }
        rmax0 = fmaxf(rmax0, __shfl_xor_sync(0xffffffffu, rmax0, 1));
        rmax0 = fmaxf(rmax0, __shfl_xor_sync(0xffffffffu, rmax0, 2));
        rmax1 = fmaxf(rmax1, __shfl_xor_sync(0xffffffffu, rmax1, 1));
        rmax1 = fmaxf(rmax1, __shfl_xor_sync(0xffffffffu, rmax1, 2));
        float m0n = fmaxf(m0, rmax0), m1n = fmaxf(m1, rmax1);
        float cr0 = __expf(m0 - m0n), cr1 = __expf(m1 - m1n);
        float rs0 = 0.0f, rs1 = 0.0f;
        #pragma unroll
        for (int ni = 0; ni < 8; ni++) {
            p[ni][0] = __expf(p[ni][0] - m0n);
            p[ni][1] = __expf(p[ni][1] - m0n);
            p[ni][2] = __expf(p[ni][2] - m1n);
            p[ni][3] = __expf(p[ni][3] - m1n);
            rs0 += p[ni][0] + p[ni][1];
            rs1 += p[ni][2] + p[ni][3];
        }
        rs0 += __shfl_xor_sync(0xffffffffu, rs0, 1);
        rs0 += __shfl_xor_sync(0xffffffffu, rs0, 2);
        rs1 += __shfl_xor_sync(0xffffffffu, rs1, 1);
        rs1 += __shfl_xor_sync(0xffffffffu, rs1, 2);
        l0 = l0 * cr0 + rs0;  m0 = m0n;
        l1 = l1 * cr1 + rs1;  m1 = m1n;
        #pragma unroll
        for (int ni = 0; ni < 16; ni++) {
            oacc[ni][0] *= cr0; oacc[ni][1] *= cr0;
            oacc[ni][2] *= cr1; oacc[ni][3] *= cr1;
        }
        uint32_t pf[4][4];
        #pragma unroll
        for (int t = 0; t < 4; t++) {
            pf[t][0] = packf2(p[2 * t][0],     p[2 * t][1]);
            pf[t][1] = packf2(p[2 * t][2],     p[2 * t][3]);
            pf[t][2] = packf2(p[2 * t + 1][0], p[2 * t + 1][1]);
            pf[t][3] = packf2(p[2 * t + 1][2], p[2 * t + 1][3]);
        }

        // ---- O += P V ----
        #pragma unroll
        for (int t = 0; t < 4; t++) {
            #pragma unroll
            for (int nb = 0; nb < 8; nb++) {
                uint32_t t4[4];
                ldm4t(t4, smaddr(&Vb[t * 16 + vt_r][nb * 16 + vt_c]));
                mma_f16(oacc[2 * nb],     pf[t], t4);
                mma_f16(oacc[2 * nb + 1], pf[t], t4 + 2);
            }
        }

        __syncthreads();
        if (c + 2 < 8) {
            load_tile(Kst(st), g_Kh + (size_t)(krow0 + (c + 2) * 64) * Hd + hoff);
            load_tile(Vst(st), g_Vh + (size_t)(krow0 + (c + 2) * 64) * Hd + hoff);
        }
    }

    float i0 = 1.0f / l0, i1 = 1.0f / l1;
    const int row = qrow0 + wid * 16 + g;
    #pragma unroll
    for (int ni = 0; ni < 16; ni++) {
        int col = hoff + ni * 8 + 2 * tig;
        *(__half2*)(g_ctxh + (size_t)row * Hd + col) =
            __floats2half2_rn(oacc[ni][0] * i0, oacc[ni][1] * i0);
        *(__half2*)(g_ctxh + (size_t)(row + 8) * Hd + col) =
            __floats2half2_rn(oacc[ni][2] * i1, oacc[ni][3] * i1);
    }
}

// =====================================================================
// LayerNorm (input already includes residual): out = LN(x) * gamma + beta
// =====================================================================
__global__ void __launch_bounds__(256) ln_kernel(
    const float* __restrict__ x_in,
    const float* __restrict__ gamma, const float* __restrict__ beta,
    float* __restrict__ out)
{
    const int row = blockIdx.x, t = threadIdx.x;
    const float4* a4 = (const float4*)(x_in + (size_t)row * Hd);

    float4 xv[2];
    float s = 0.0f, ss = 0.0f;
    #pragma unroll
    for (int p = 0; p < 2; p++) {
        int i = t + p * 256;
        float4 x = a4[i];
        xv[p] = x;
        s  += x.x + x.y + x.z + x.w;
        ss += x.x * x.x + x.y * x.y + x.z * x.z + x.w * x.w;
    }
    __shared__ float rs[8], rss[8];
    #pragma unroll
    for (int o = 16; o > 0; o >>= 1) {
        s  += __shfl_xor_sync(0xffffffffu, s, o);
        ss += __shfl_xor_sync(0xffffffffu, ss, o);
    }
    if ((t & 31) == 0) { rs[t >> 5] = s; rss[t >> 5] = ss; }
    __syncthreads();
    float ts = 0.0f, tss = 0.0f;
    #pragma unroll
    for (int i = 0; i < 8; i++) { ts += rs[i]; tss += rss[i]; }
    const float mean = ts * (1.0f / Hd);
    const float var  = tss * (1.0f / Hd) - mean * mean;
    const float inv  = rsqrtf(var + 1e-5f);

    const float4* g4 = (const float4*)gamma;
    const float4* b4 = (const float4*)beta;
    float4* o4 = (float4*)(out + (size_t)row * Hd);
    #pragma unroll
    for (int p = 0; p < 2; p++) {
        int i = t + p * 256;
        float4 gv = g4[i], bv = b4[i], x = xv[p];
        o4[i] = make_float4((x.x - mean) * inv * gv.x + bv.x,
                            (x.y - mean) * inv * gv.y + bv.y,
                            (x.z - mean) * inv * gv.z + bv.z,
                            (x.w - mean) * inv * gv.w + bv.w);
    }
}

// =====================================================================
// launcher
// =====================================================================
extern "C" void kernel_launch(void* const* d_in, const int* in_sizes, int n_in,
                              void* d_out, int out_size)
{
    const float* hidden = (const float*)d_in[0];
    const float* audio  = (const float*)d_in[1];
    const float* amask  = (const float*)d_in[2];
    const float* Wq = (const float*)d_in[3];
    const float* bq = (const float*)d_in[4];
    const float* Wk = (const float*)d_in[5];
    const float* bk = (const float*)d_in[6];
    const float* Wv = (const float*)d_in[7];
    const float* bv = (const float*)d_in[8];
    const float* Wo = (const float*)d_in[9];
    const float* bo = (const float*)d_in[10];
    const float* gamma = (const float*)d_in[11];
    const float* beta  = (const float*)d_in[12];
    float* out = (float*)d_out;

    __half *hidh, *audh, *Wh, *Qh, *Kh, *Vh, *ctxh;
    float* attp;
    cudaGetSymbolAddress((void**)&hidh, g_hidh);
    cudaGetSymbolAddress((void**)&audh, g_audh);
    cudaGetSymbolAddress((void**)&Wh,   g_Wh);
    cudaGetSymbolAddress((void**)&Qh,   g_Qh);
    cudaGetSymbolAddress((void**)&Kh,   g_Kh);
    cudaGetSymbolAddress((void**)&Vh,   g_Vh);
    cudaGetSymbolAddress((void**)&ctxh, g_ctxh);
    cudaGetSymbolAddress((void**)&attp, g_att);
    __half* WqH = Wh;
    __half* WkH = Wh + (size_t)Hd * Hd;
    __half* WvH = Wh + 2 * (size_t)Hd * Hd;
    __half* WoH = Wh + 3 * (size_t)Hd * Hd;

    cudaFuncSetAttribute(attn_kernel, cudaFuncAttributeMaxDynamicSharedMemorySize,
                         ATTN_SMEM_BYTES);
    cudaFuncSetAttribute(gemm_h_kernel<true, false>,
                         cudaFuncAttributeMaxDynamicSharedMemorySize, GEMM_SMEM_BYTES);
    cudaFuncSetAttribute(gemm_h_kernel<false, true>,
                         cudaFuncAttributeMaxDynamicSharedMemorySize, GEMM_SMEM_BYTES);

    // converts (weights stay natural [k][n]; no transpose)
    f2h_kernel<<<(Bd * Sd * Hd) / 1024, 256>>>(hidden, hidh);
    f2h_kernel<<<(Bd * Ad * Hd) / 1024, 256>>>(audio, audh);
    f2h_kernel<<<(Hd * Hd) / 1024, 256>>>(Wq, WqH);
    f2h_kernel<<<(Hd * Hd) / 1024, 256>>>(Wk, WkH);
    f2h_kernel<<<(Hd * Hd) / 1024, 256>>>(Wv, WvH);
    f2h_kernel<<<(Hd * Hd) / 1024, 256>>>(Wo, WoH);

    gemm_h_kernel<true, false><<<dim3(16, (Bd * Sd) / 128), 256, GEMM_SMEM_BYTES>>>(
        hidh, WqH, bq, nullptr, Qh);
    gemm_h_kernel<true, false><<<dim3(16, (Bd * Ad) / 128), 256, GEMM_SMEM_BYTES>>>(
        audh, WkH, bk, nullptr, Kh);
    gemm_h_kernel<true, false><<<dim3(16, (Bd * Ad) / 128), 256, GEMM_SMEM_BYTES>>>(
        audh, WvH, bv, nullptr, Vh);
    attn_kernel<<<Bd * NHd * (Sd / 64), 128, ATTN_SMEM_BYTES>>>(amask);
    // out_proj + residual fused
    gemm_h_kernel<false, true><<<dim3(16, (Bd * Sd) / 128), 256, GEMM_SMEM_BYTES>>>(
        ctxh, WoH, bo, hidden, attp);
    ln_kernel<<<Bd * Sd, 256>>>(attp, gamma, beta, out);
}

// round 15
// speedup vs baseline: 2.4907x; 1.0707x over previous
#include <cuda_runtime.h>
#include <cuda_fp16.h>
#include <cstdint>

#define Hd   2048
#define NHd  16
#define DHd  128
#define Bd   4
#define Sd   2048
#define Ad   512

// ---------------- scratch (static device arrays; no allocation) ----------------
__device__ __half g_hidh[(size_t)Bd * Sd * Hd];
__device__ __half g_audh[(size_t)Bd * Ad * Hd];
__device__ __half g_Wh[4][(size_t)Hd * Hd];       // fp16 weights, natural [k][n]
__device__ __half g_Qh[(size_t)Bd * Sd * Hd];
__device__ __half g_Kh[(size_t)Bd * Ad * Hd];
__device__ __half g_Vh[(size_t)Bd * Ad * Hd];
__device__ __half g_ctxh[(size_t)Bd * Sd * Hd];
__device__ float  g_att[(size_t)Bd * Sd * Hd];    // out_proj + residual (fp32)

// ---------------- helpers ----------------
__device__ __forceinline__ void cp16(void* dst, const void* src) {
    uint32_t d = (uint32_t)__cvta_generic_to_shared(dst);
    asm volatile("cp.async.cg.shared.global [%0], [%1], 16;\n" :: "r"(d), "l"(src));
}
#define CP_COMMIT asm volatile("cp.async.commit_group;\n" ::: "memory")
#define CP_WAIT0  asm volatile("cp.async.wait_group 0;\n" ::: "memory")
#define CP_WAIT1  asm volatile("cp.async.wait_group 1;\n" ::: "memory")
#define CP_WAIT2  asm volatile("cp.async.wait_group 2;\n" ::: "memory")

__device__ __forceinline__ uint32_t smaddr(const void* p) {
    return (uint32_t)__cvta_generic_to_shared(p);
}

__device__ __forceinline__ void ldm4(uint32_t r[4], uint32_t a) {
    asm volatile("ldmatrix.sync.aligned.m8n8.x4.shared.b16 {%0,%1,%2,%3}, [%4];"
                 : "=r"(r[0]), "=r"(r[1]), "=r"(r[2]), "=r"(r[3]) : "r"(a));
}
__device__ __forceinline__ void ldm4t(uint32_t r[4], uint32_t a) {
    asm volatile("ldmatrix.sync.aligned.m8n8.x4.trans.shared.b16 {%0,%1,%2,%3}, [%4];"
                 : "=r"(r[0]), "=r"(r[1]), "=r"(r[2]), "=r"(r[3]) : "r"(a));
}

__device__ __forceinline__ void mma_f16(float c[4], const uint32_t a[4], const uint32_t b[2]) {
    asm volatile(
        "mma.sync.aligned.m16n8k16.row.col.f32.f16.f16.f32 "
        "{%0,%1,%2,%3}, {%4,%5,%6,%7}, {%8,%9}, {%0,%1,%2,%3};"
        : "+f"(c[0]), "+f"(c[1]), "+f"(c[2]), "+f"(c[3])
        : "r"(a[0]), "r"(a[1]), "r"(a[2]), "r"(a[3]), "r"(b[0]), "r"(b[1]));
}

__device__ __forceinline__ uint32_t packf2(float a, float b) {
    __half2 h = __floats2half2_rn(a, b);
    return *(uint32_t*)&h;
}

// =====================================================================
// One-shot convert: hidden, audio, 4 weights -> fp16 (range-selected)
// block = 256 thr x 4 floats = 1024 floats
//   [0, 16384)        hidden  (16.78M)
//   [16384, 20480)    audio   (4.19M)
//   [20480, 36864)    weights (4 x 4.19M, contiguous dst g_Wh)
// =====================================================================
__global__ void __launch_bounds__(256) convert_all_kernel(
    const float* __restrict__ hid, const float* __restrict__ aud,
    const float* __restrict__ w0, const float* __restrict__ w1,
    const float* __restrict__ w2, const float* __restrict__ w3)
{
    int b = blockIdx.x;
    const float* src;
    __half* dst;
    int off;
    if (b < 16384)      { src = hid; dst = g_hidh; off = b; }
    else if (b < 20480) { src = aud; dst = g_audh; off = b - 16384; }
    else {
        int t  = b - 20480;
        int wi = t >> 12;            // 4096 blocks per weight
        off    = t & 4095;
        src = (wi == 0) ? w0 : (wi == 1) ? w1 : (wi == 2) ? w2 : w3;
        dst = g_Wh[wi];
    }
    int i = off * 256 + threadIdx.x;
    float4 v = ((const float4*)src)[i];
    __half2* o2 = (__half2*)dst;
    o2[2 * i]     = __floats2half2_rn(v.x, v.y);
    o2[2 * i + 1] = __floats2half2_rn(v.z, v.w);
}

// =====================================================================
// fp16 GEMM body: C[128x128 tile] = X @ W + bias (+ optional fp32 residual)
//   X fp16 [m][k]; W fp16 [k][n] natural layout (B-frags via ldmatrix.trans).
//   BK=32, 256 threads (8 warps 2x4, warp tile 64x32), 3-stage cp.async.
// =====================================================================
#define GEMM_SMEM_BYTES (3 * 128 * 40 * 2 + 3 * 32 * 136 * 2)   // 56832

template<bool HALF_OUT, bool RES>
__device__ __forceinline__ void gemm_body(
    char* gsm,
    const __half* __restrict__ X, const __half* __restrict__ W,
    const float* __restrict__ bias, const float* __restrict__ res,
    void* __restrict__ Cout, int m0, int n0)
{
    __half (*As)[128][40] = (__half (*)[128][40])gsm;             // [3][128][40]
    __half (*Bs)[32][136] = (__half (*)[32][136])(gsm + 30720);   // [3][32][136]

    const int tid  = threadIdx.x;
    const int lane = tid & 31, wid = tid >> 5;
    const int g    = lane >> 2, tig = lane & 3;
    const int wm   = wid >> 2,  wn  = wid & 3;

    const int ar = tid >> 1;
    const int ac = (tid & 1) * 16;
    const int brow = tid >> 3;
    const int bcol = (tid & 7) * 8;

    const int lm_r = (lane & 7) + ((lane >> 3) & 1) * 8;   // A (non-trans)
    const int lm_c = (lane >> 4) * 8;
    const int vt_r = (lane & 7) + ((lane >> 3) & 1) * 8;   // B (trans): rows = k
    const int vt_c = (lane >> 4) * 8;

    float acc[4][4][4];
    #pragma unroll
    for (int mi = 0; mi < 4; mi++)
        #pragma unroll
        for (int ni = 0; ni < 4; ni++)
            #pragma unroll
            for (int j = 0; j < 4; j++) acc[mi][ni][j] = 0.0f;

    auto load_stage = [&](int st, int k0) {
        const __half* xs = X + (size_t)(m0 + ar) * Hd + k0 + ac;
        cp16(&As[st][ar][ac],     xs);
        cp16(&As[st][ar][ac + 8], xs + 8);
        const __half* ws = W + (size_t)(k0 + brow) * Hd + n0 + bcol;
        cp16(&Bs[st][brow][bcol],      ws);
        cp16(&Bs[st][brow][bcol + 64], ws + 64);
        CP_COMMIT;
    };

    load_stage(0, 0);
    load_stage(1, 32);

    #pragma unroll 1
    for (int c = 0; c < Hd / 32; c++) {
        const int st = c % 3;
        CP_WAIT1;
        __syncthreads();
        if (c + 2 < Hd / 32) load_stage((c + 2) % 3, (c + 2) * 32);

        #pragma unroll
        for (int kk = 0; kk < 32; kk += 16) {
            uint32_t af[4][4];
            #pragma unroll
            for (int mi = 0; mi < 4; mi++)
                ldm4(af[mi], smaddr(&As[st][wm * 64 + mi * 16 + lm_r][kk + lm_c]));
            uint32_t bf[4][2];
            #pragma unroll
            for (int nb = 0; nb < 2; nb++) {
                uint32_t t4[4];
                ldm4t(t4, smaddr(&Bs[st][kk + vt_r][wn * 32 + nb * 16 + vt_c]));
                bf[2 * nb][0]     = t4[0];
                bf[2 * nb][1]     = t4[1];
                bf[2 * nb + 1][0] = t4[2];
                bf[2 * nb + 1][1] = t4[3];
            }
            #pragma unroll
            for (int mi = 0; mi < 4; mi++)
                #pragma unroll
                for (int ni = 0; ni < 4; ni++)
                    mma_f16(acc[mi][ni], af[mi], bf[ni]);
        }
    }

    #pragma unroll
    for (int mi = 0; mi < 4; mi++) {
        #pragma unroll
        for (int ni = 0; ni < 4; ni++) {
            int r = m0 + wm * 64 + mi * 16 + g;
            int c = n0 + wn * 32 + ni * 8 + tig * 2;
            float v0 = acc[mi][ni][0] + bias[c];
            float v1 = acc[mi][ni][1] + bias[c + 1];
            float v2 = acc[mi][ni][2] + bias[c];
            float v3 = acc[mi][ni][3] + bias[c + 1];
            if (RES) {
                float2 r0 = *(const float2*)(res + (size_t)r * Hd + c);
                float2 r1 = *(const float2*)(res + (size_t)(r + 8) * Hd + c);
                v0 += r0.x; v1 += r0.y; v2 += r1.x; v3 += r1.y;
            }
            if (HALF_OUT) {
                __half* C = (__half*)Cout;
                *(__half2*)(C + (size_t)r * Hd + c)       = __floats2half2_rn(v0, v1);
                *(__half2*)(C + (size_t)(r + 8) * Hd + c) = __floats2half2_rn(v2, v3);
            } else {
                float* C = (float*)Cout;
                *(float2*)(C + (size_t)r * Hd + c)       = make_float2(v0, v1);
                *(float2*)(C + (size_t)(r + 8) * Hd + c) = make_float2(v2, v3);
            }
        }
    }
}

// =====================================================================
// Merged Q/K/V projection launch: 1536 CTAs
//   [0, 1024):    Q tiles  (64 m x 16 n), X=hidden
//   [1024, 1280): K tiles  (16 m x 16 n), X=audio
//   [1280, 1536): V tiles
// =====================================================================
__global__ void __launch_bounds__(256) qkv_kernel(
    const float* __restrict__ bq, const float* __restrict__ bk,
    const float* __restrict__ bv)
{
    extern __shared__ char gsm[];
    const int bid = blockIdx.x;
    const __half* X;
    const __half* W;
    const float* bias;
    __half* out;
    int m0, n0;
    if (bid < 1024) {
        X = g_hidh; W = g_Wh[0]; bias = bq; out = g_Qh;
        m0 = (bid >> 4) * 128; n0 = (bid & 15) * 128;
    } else if (bid < 1280) {
        int t = bid - 1024;
        X = g_audh; W = g_Wh[1]; bias = bk; out = g_Kh;
        m0 = (t >> 4) * 128; n0 = (t & 15) * 128;
    } else {
        int t = bid - 1280;
        X = g_audh; W = g_Wh[2]; bias = bv; out = g_Vh;
        m0 = (t >> 4) * 128; n0 = (t & 15) * 128;
    }
    gemm_body<true, false>(gsm, X, W, bias, nullptr, out, m0, n0);
}

// =====================================================================
// Output projection + residual: fp32 out
// =====================================================================
__global__ void __launch_bounds__(256) wo_kernel(
    const float* __restrict__ bo, const float* __restrict__ hidden)
{
    extern __shared__ char gsm[];
    gemm_body<false, true>(gsm, g_ctxh, g_Wh[3], bo, hidden, g_att,
                           (int)(blockIdx.y * 128), (int)(blockIdx.x * 128));
}

// =====================================================================
// Flash attention (unchanged from R14): CTA = 64 q-rows x one head,
// 128 threads, Q frags direct from gmem, double-buffered K/V.
// smem: K[2] + V[2] (4 x 17408) + mv 512f = 71,680 B -> 3 CTAs/SM
// =====================================================================
#define AT_K   0
#define AT_V   34816
#define AT_MV  69632
#define ATTN_SMEM_BYTES 71680

__global__ void __launch_bounds__(128) attn_kernel(const float* __restrict__ mask)
{
    extern __shared__ char smc[];
    float* mv = (float*)(smc + AT_MV);

    const int tid  = threadIdx.x;
    const int lane = tid & 31, wid = tid >> 5;
    const int g    = lane >> 2, tig = lane & 3;

    const int bx = blockIdx.x;
    const int qt = bx & 31;
    const int h  = (bx >> 5) & 15;
    const int b  = bx >> 9;
    const int qrow0 = b * Sd + qt * 64;
    const int krow0 = b * Ad;
    const int hoff  = h * DHd;
    const float scale = 0.0883883476483184f;

    auto load_tile = [&](char* dstbase, const __half* src_base) {
        __half (*dst)[136] = (__half (*)[136])dstbase;
        #pragma unroll
        for (int p = 0; p < 8; p++) {
            int i = tid + p * 128;
            int r = i >> 4, c = (i & 15) * 8;
            cp16(&dst[r][c], src_base + (size_t)r * Hd + c);
        }
        CP_COMMIT;
    };
    auto Kst = [&](int st) { return smc + AT_K + st * 17408; };
    auto Vst = [&](int st) { return smc + AT_V + st * 17408; };

    load_tile(Kst(0), g_Kh + (size_t)krow0 * Hd + hoff);
    load_tile(Vst(0), g_Vh + (size_t)krow0 * Hd + hoff);
    load_tile(Kst(1), g_Kh + (size_t)(krow0 + 64) * Hd + hoff);
    load_tile(Vst(1), g_Vh + (size_t)(krow0 + 64) * Hd + hoff);
    #pragma unroll
    for (int p = 0; p < 4; p++) {
        int i = tid + p * 128;
        mv[i] = mask[b * Ad + i] * -10000.0f;
    }

    uint32_t qf[8][4];
    {
        const __half* q0 = g_Qh + (size_t)(qrow0 + wid * 16 + g) * Hd + hoff;
        const __half* q1 = q0 + 8 * Hd;
        #pragma unroll
        for (int kk = 0; kk < 8; kk++) {
            qf[kk][0] = *(const uint32_t*)(q0 + kk * 16 + 2 * tig);
            qf[kk][1] = *(const uint32_t*)(q1 + kk * 16 + 2 * tig);
            qf[kk][2] = *(const uint32_t*)(q0 + kk * 16 + 2 * tig + 8);
            qf[kk][3] = *(const uint32_t*)(q1 + kk * 16 + 2 * tig + 8);
        }
    }

    float oacc[16][4];
    #pragma unroll
    for (int ni = 0; ni < 16; ni++)
        #pragma unroll
        for (int j = 0; j < 4; j++) oacc[ni][j] = 0.0f;
    float m0 = -1e30f, m1 = -1e30f, l0 = 0.0f, l1 = 0.0f;

    const int kq_r = (lane & 7) + (lane >> 4) * 8;
    const int kq_c = ((lane >> 3) & 1) * 8;
    const int vt_r = (lane & 7) + ((lane >> 3) & 1) * 8;
    const int vt_c = (lane >> 4) * 8;

    #pragma unroll 1
    for (int c = 0; c < 8; c++) {
        const int st = c & 1;
        if (c < 6) { CP_WAIT2; } else { CP_WAIT0; }
        __syncthreads();
        const __half (*Kb)[136] = (const __half (*)[136])Kst(st);
        const __half (*Vb)[136] = (const __half (*)[136])Vst(st);

        float sacc[8][4];
        #pragma unroll
        for (int ni = 0; ni < 8; ni++)
            #pragma unroll
            for (int j = 0; j < 4; j++) sacc[ni][j] = 0.0f;

        #pragma unroll
        for (int kk = 0; kk < 8; kk++) {
            uint32_t bf[8][2];
            #pragma unroll
            for (int nb = 0; nb < 4; nb++) {
                uint32_t t4[4];
                ldm4(t4, smaddr(&Kb[nb * 16 + kq_r][kk * 16 + kq_c]));
                bf[2 * nb][0]     = t4[0];
                bf[2 * nb][1]     = t4[1];
                bf[2 * nb + 1][0] = t4[2];
                bf[2 * nb + 1][1] = t4[3];
            }
            #pragma unroll
            for (int ni = 0; ni < 8; ni++)
                mma_f16(sacc[ni], qf[kk], bf[ni]);
        }

        const int cb = c * 64;
        float p[8][4];
        float rmax0 = -1e30f, rmax1 = -1e30f;
        #pragma unroll
        for (int ni = 0; ni < 8; ni++) {
            float mva = mv[cb + ni * 8 + 2 * tig];
            float mvb = mv[cb + ni * 8 + 2 * tig + 1];
            p[ni][0] = sacc[ni][0] * scale + mva;
            p[ni][1] = sacc[ni][1] * scale + mvb;
            p[ni][2] = sacc[ni][2] * scale + mva;
            p[ni][3] = sacc[ni][3] * scale + mvb;
            rmax0 = fmaxf(rmax0, fmaxf(p[ni][0], p[ni][1]));
            rmax1 = fmaxf(rmax1, fmaxf(p[ni][2], p[ni][3]));
        }
        rmax0 = fmaxf(rmax0, __shfl_xor_sync(0xffffffffu, rmax0, 1));
        rmax0 = fmaxf(rmax0, __shfl_xor_sync(0xffffffffu, rmax0, 2));
        rmax1 = fmaxf(rmax1, __shfl_xor_sync(0xffffffffu, rmax1, 1));
        rmax1 = fmaxf(rmax1, __shfl_xor_sync(0xffffffffu, rmax1, 2));
        float m0n = fmaxf(m0, rmax0), m1n = fmaxf(m1, rmax1);
        float cr0 = __expf(m0 - m0n), cr1 = __expf(m1 - m1n);
        float rs0 = 0.0f, rs1 = 0.0f;
        #pragma unroll
        for (int ni = 0; ni < 8; ni++) {
            p[ni][0] = __expf(p[ni][0] - m0n);
            p[ni][1] = __expf(p[ni][1] - m0n);
            p[ni][2] = __expf(p[ni][2] - m1n);
            p[ni][3] = __expf(p[ni][3] - m1n);
            rs0 += p[ni][0] + p[ni][1];
            rs1 += p[ni][2] + p[ni][3];
        }
        rs0 += __shfl_xor_sync(0xffffffffu, rs0, 1);
        rs0 += __shfl_xor_sync(0xffffffffu, rs0, 2);
        rs1 += __shfl_xor_sync(0xffffffffu, rs1, 1);
        rs1 += __shfl_xor_sync(0xffffffffu, rs1, 2);
        l0 = l0 * cr0 + rs0;  m0 = m0n;
        l1 = l1 * cr1 + rs1;  m1 = m1n;
        #pragma unroll
        for (int ni = 0; ni < 16; ni++) {
            oacc[ni][0] *= cr0; oacc[ni][1] *= cr0;
            oacc[ni][2] *= cr1; oacc[ni][3] *= cr1;
        }
        uint32_t pf[4][4];
        #pragma unroll
        for (int t = 0; t < 4; t++) {
            pf[t][0] = packf2(p[2 * t][0],     p[2 * t][1]);
            pf[t][1] = packf2(p[2 * t][2],     p[2 * t][3]);
            pf[t][2] = packf2(p[2 * t + 1][0], p[2 * t + 1][1]);
            pf[t][3] = packf2(p[2 * t + 1][2], p[2 * t + 1][3]);
        }

        #pragma unroll
        for (int t = 0; t < 4; t++) {
            #pragma unroll
            for (int nb = 0; nb < 8; nb++) {
                uint32_t t4[4];
                ldm4t(t4, smaddr(&Vb[t * 16 + vt_r][nb * 16 + vt_c]));
                mma_f16(oacc[2 * nb],     pf[t], t4);
                mma_f16(oacc[2 * nb + 1], pf[t], t4 + 2);
            }
        }

        __syncthreads();
        if (c + 2 < 8) {
            load_tile(Kst(st), g_Kh + (size_t)(krow0 + (c + 2) * 64) * Hd + hoff);
            load_tile(Vst(st), g_Vh + (size_t)(krow0 + (c + 2) * 64) * Hd + hoff);
        }
    }

    float i0 = 1.0f / l0, i1 = 1.0f / l1;
    const int row = qrow0 + wid * 16 + g;
    #pragma unroll
    for (int ni = 0; ni < 16; ni++) {
        int col = hoff + ni * 8 + 2 * tig;
        *(__half2*)(g_ctxh + (size_t)row * Hd + col) =
            __floats2half2_rn(oacc[ni][0] * i0, oacc[ni][1] * i0);
        *(__half2*)(g_ctxh + (size_t)(row + 8) * Hd + col) =
            __floats2half2_rn(oacc[ni][2] * i1, oacc[ni][3] * i1);
    }
}

// =====================================================================
// LayerNorm (input already includes residual)
// =====================================================================
__global__ void __launch_bounds__(256) ln_kernel(
    const float* __restrict__ gamma, const float* __restrict__ beta,
    float* __restrict__ out)
{
    const int row = blockIdx.x, t = threadIdx.x;
    const float4* a4 = (const float4*)(g_att + (size_t)row * Hd);

    float4 xv[2];
    float s = 0.0f, ss = 0.0f;
    #pragma unroll
    for (int p = 0; p < 2; p++) {
        int i = t + p * 256;
        float4 x = a4[i];
        xv[p] = x;
        s  += x.x + x.y + x.z + x.w;
        ss += x.x * x.x + x.y * x.y + x.z * x.z + x.w * x.w;
    }
    __shared__ float rs[8], rss[8];
    #pragma unroll
    for (int o = 16; o > 0; o >>= 1) {
        s  += __shfl_xor_sync(0xffffffffu, s, o);
        ss += __shfl_xor_sync(0xffffffffu, ss, o);
    }
    if ((t & 31) == 0) { rs[t >> 5] = s; rss[t >> 5] = ss; }
    __syncthreads();
    float ts = 0.0f, tss = 0.0f;
    #pragma unroll
    for (int i = 0; i < 8; i++) { ts += rs[i]; tss += rss[i]; }
    const float mean = ts * (1.0f / Hd);
    const float var  = tss * (1.0f / Hd) - mean * mean;
    const float inv  = rsqrtf(var + 1e-5f);

    const float4* g4 = (const float4*)gamma;
    const float4* b4 = (const float4*)beta;
    float4* o4 = (float4*)(out + (size_t)row * Hd);
    #pragma unroll
    for (int p = 0; p < 2; p++) {
        int i = t + p * 256;
        float4 gv = g4[i], bv = b4[i], x = xv[p];
        o4[i] = make_float4((x.x - mean) * inv * gv.x + bv.x,
                            (x.y - mean) * inv * gv.y + bv.y,
                            (x.z - mean) * inv * gv.z + bv.z,
                            (x.w - mean) * inv * gv.w + bv.w);
    }
}

// =====================================================================
// launcher: 5 kernels total
// =====================================================================
extern "C" void kernel_launch(void* const* d_in, const int* in_sizes, int n_in,
                              void* d_out, int out_size)
{
    const float* hidden = (const float*)d_in[0];
    const float* audio  = (const float*)d_in[1];
    const float* amask  = (const float*)d_in[2];
    const float* Wq = (const float*)d_in[3];
    const float* bq = (const float*)d_in[4];
    const float* Wk = (const float*)d_in[5];
    const float* bk = (const float*)d_in[6];
    const float* Wv = (const float*)d_in[7];
    const float* bv = (const float*)d_in[8];
    const float* Wo = (const float*)d_in[9];
    const float* bo = (const float*)d_in[10];
    const float* gamma = (const float*)d_in[11];
    const float* beta  = (const float*)d_in[12];
    float* out = (float*)d_out;

    cudaFuncSetAttribute(attn_kernel, cudaFuncAttributeMaxDynamicSharedMemorySize,
                         ATTN_SMEM_BYTES);
    cudaFuncSetAttribute(qkv_kernel, cudaFuncAttributeMaxDynamicSharedMemorySize,
                         GEMM_SMEM_BYTES);
    cudaFuncSetAttribute(wo_kernel, cudaFuncAttributeMaxDynamicSharedMemorySize,
                         GEMM_SMEM_BYTES);

    // 1) all converts in one launch
    convert_all_kernel<<<36864, 256>>>(hidden, audio, Wq, Wk, Wv, Wo);
    // 2) Q, K, V projections in one launch
    qkv_kernel<<<1536, 256, GEMM_SMEM_BYTES>>>(bq, bk, bv);
    // 3) fused flash attention
    attn_kernel<<<Bd * NHd * (Sd / 64), 128, ATTN_SMEM_BYTES>>>(amask);
    // 4) out_proj + residual
    wo_kernel<<<dim3(16, (Bd * Sd) / 128), 256, GEMM_SMEM_BYTES>>>(bo, hidden);
    // 5) LayerNorm
    ln_kernel<<<Bd * Sd, 256>>>(gamma, beta, out);
}